// round 3
// baseline (speedup 1.0000x reference)
#include <cuda_runtime.h>
#include <math.h>

#define NB 8
#define CH 128
#define HH 112
#define WW 112
#define HW (HH*WW)          // 12544
#define NC (NB*CH)          // 1024
#define TOT (NB*CH*HW)      // 12,845,056
#define PP 37               // pooled dim (112/3)
#define NPOOL (PP*PP)       // 1369

// ---- scratch (device globals; no allocation in kernel_launch) ----
__device__ float g_z[TOT];      // sym-conv output
__device__ float g_y[TOT];      // dwconv output
__device__ float g_wsym[CH*CH];
__device__ float g_gap[NC];
__device__ float g_ent[NB];
__device__ float g_gates[NB*3];
__device__ float g_sum[NC];     // later: mean
__device__ float g_sumsq[NC];   // later: rstd*gamma

// ================= copy x -> h =================
__global__ void copy_kernel(const float* __restrict__ x, float* __restrict__ h) {
    int i = blockIdx.x * 256 + threadIdx.x;
    ((float4*)h)[i] = ((const float4*)x)[i];
}

// ================= symmetrize W =================
__global__ void wsym_kernel(const float* __restrict__ W) {
    int i = blockIdx.x * 256 + threadIdx.x;   // 16384
    int d = i >> 7, c = i & 127;
    g_wsym[i] = 0.5f * (W[d*CH + c] + W[c*CH + d]);
}

// ================= clear accumulators =================
__global__ void clear_kernel() {
    int i = threadIdx.x;  // 1024
    if (i < NB) g_ent[i] = 0.f;
    g_sum[i] = 0.f;
    g_sumsq[i] = 0.f;
}

// ================= GAP: per-(n,c) spatial mean of h =================
__global__ void gap_kernel(const float* __restrict__ h) {
    int nc = blockIdx.x;
    const float4* p = (const float4*)(h + (size_t)nc * HW);
    float s = 0.f;
    for (int i = threadIdx.x; i < HW/4; i += 256) {
        float4 v = p[i];
        s += (v.x + v.y) + (v.z + v.w);
    }
    __shared__ float red[256];
    red[threadIdx.x] = s;
    __syncthreads();
    for (int o = 128; o > 0; o >>= 1) {
        if (threadIdx.x < o) red[threadIdx.x] += red[threadIdx.x + o];
        __syncthreads();
    }
    if (threadIdx.x == 0) g_gap[nc] = red[0] * (1.f / (float)HW);
}

// ================= entropy over pooled channel-softmax =================
// one warp per pooled position; lane j handles channels lane, lane+32, lane+64, lane+96
__global__ void ent_kernel(const float* __restrict__ h) {
    int warp = (blockIdx.x * blockDim.x + threadIdx.x) >> 5;  // [0, NB*NPOOL)
    int lane = threadIdx.x & 31;
    int n   = warp / NPOOL;
    int rem = warp - n * NPOOL;
    int py = rem / PP, px = rem - py * PP;
    const float* base = h + (size_t)n * CH * HW + (py*3) * WW + px*3;
    float v[4];
#pragma unroll
    for (int j = 0; j < 4; j++) {
        int c = j*32 + lane;
        const float* p = base + (size_t)c * HW;
        float s = 0.f;
#pragma unroll
        for (int r = 0; r < 3; r++) s += p[r*WW] + p[r*WW+1] + p[r*WW+2];
        v[j] = s * (1.f/9.f);
    }
    float m = fmaxf(fmaxf(v[0], v[1]), fmaxf(v[2], v[3]));
#pragma unroll
    for (int o = 16; o > 0; o >>= 1) m = fmaxf(m, __shfl_xor_sync(0xffffffffu, m, o));
    float s = 0.f;
#pragma unroll
    for (int j = 0; j < 4; j++) s += expf(v[j] - m);
#pragma unroll
    for (int o = 16; o > 0; o >>= 1) s += __shfl_xor_sync(0xffffffffu, s, o);
    float lse = m + logf(s);
    float e = 0.f;
#pragma unroll
    for (int j = 0; j < 4; j++) {
        float lp = v[j] - lse;
        e -= expf(lp) * lp;
    }
#pragma unroll
    for (int o = 16; o > 0; o >>= 1) e += __shfl_xor_sync(0xffffffffu, e, o);
    if (lane == 0) atomicAdd(&g_ent[n], e);
}

// ================= gate logits + softmax =================
__global__ void gate_kernel(const float* __restrict__ gW, const float* __restrict__ gb,
                            const float* __restrict__ gwe) {
    __shared__ float lg[NB][3];
    int t = threadIdx.x;  // 32 threads
    if (t < NB*3) {
        int n = t / 3, i = t - n*3;
        float s = 0.f;
        for (int c = 0; c < CH; c++) s += g_gap[n*CH + c] * gW[c*3 + i];
        float ent = g_ent[n] * (1.f / (float)NPOOL);
        lg[n][i] = s + gb[i] + ent * gwe[i];
    }
    __syncwarp();
    if (t < NB) {
        float a = lg[t][0], b = lg[t][1], c = lg[t][2];
        float m = fmaxf(a, fmaxf(b, c));
        float e0 = expf(a-m), e1 = expf(b-m), e2 = expf(c-m);
        float inv = 1.f / (e0 + e1 + e2);
        g_gates[t*3+0] = e0*inv;
        g_gates[t*3+1] = e1*inv;
        g_gates[t*3+2] = e2*inv;
    }
}

// ================= symmetric 1x1 conv: z = Wsym @ h + bias =================
// SGEMM: M=128 (all outC), N-tile = 128 pixels, K=128, BK=8, 8x8 microtile
__global__ void __launch_bounds__(256) symconv_kernel(const float* __restrict__ h,
                                                      const float* __restrict__ bias) {
    __shared__ float As[8][132];   // [k][m], padded
    __shared__ float Bs[8][128];   // [k][p]
    int n  = blockIdx.y;
    int p0 = blockIdx.x * 128;
    int tid = threadIdx.x;
    int tx = tid & 15, ty = tid >> 4;
    const float* hb = h + (size_t)n * CH * HW + p0;
    float acc[8][8];
#pragma unroll
    for (int i = 0; i < 8; i++)
#pragma unroll
        for (int j = 0; j < 8; j++) acc[i][j] = 0.f;

    for (int k0 = 0; k0 < CH; k0 += 8) {
        for (int e = tid; e < 1024; e += 256) {
            int i = e >> 3, j = e & 7;
            As[j][i] = g_wsym[i*CH + k0 + j];
        }
        for (int e = tid; e < 1024; e += 256) {
            int r = e >> 7, cc = e & 127;
            Bs[r][cc] = hb[(size_t)(k0 + r) * HW + cc];
        }
        __syncthreads();
#pragma unroll
        for (int k = 0; k < 8; k++) {
            float a[8], b[8];
            *(float4*)&a[0] = *(float4*)&As[k][ty*8];
            *(float4*)&a[4] = *(float4*)&As[k][ty*8 + 4];
            *(float4*)&b[0] = *(float4*)&Bs[k][tx*8];
            *(float4*)&b[4] = *(float4*)&Bs[k][tx*8 + 4];
#pragma unroll
            for (int i = 0; i < 8; i++)
#pragma unroll
                for (int j = 0; j < 8; j++) acc[i][j] += a[i] * b[j];
        }
        __syncthreads();
    }
    float* zb = g_z + (size_t)n * CH * HW + p0;
#pragma unroll
    for (int i = 0; i < 8; i++) {
        int m = ty*8 + i;
        float bi = bias[m];
        float4 v0, v1;
        v0.x = acc[i][0]+bi; v0.y = acc[i][1]+bi; v0.z = acc[i][2]+bi; v0.w = acc[i][3]+bi;
        v1.x = acc[i][4]+bi; v1.y = acc[i][5]+bi; v1.z = acc[i][6]+bi; v1.w = acc[i][7]+bi;
        *(float4*)&zb[(size_t)m * HW + tx*8]     = v0;
        *(float4*)&zb[(size_t)m * HW + tx*8 + 4] = v1;
    }
}

// ================= gated tri-dilated depthwise conv + IS-norm stats =================
__global__ void __launch_bounds__(256) dw_kernel(const float* __restrict__ w,
                                                 const float* __restrict__ bias) {
    int nc = blockIdx.y;
    int n = nc >> 7, c = nc & 127;
    int ty0 = (blockIdx.x >> 2) * 28, tx0 = (blockIdx.x & 3) * 28;
    __shared__ float sm[36][36];
    __shared__ float red[256];
    __shared__ float redq[256];
    const float* zb = g_z + (size_t)nc * HW;
    for (int s = threadIdx.x; s < 36*36; s += 256) {
        int sy = s / 36, sx = s - sy*36;
        int gy = ty0 - 4 + sy, gx = tx0 - 4 + sx;
        float v = 0.f;
        if ((unsigned)gy < (unsigned)HH && (unsigned)gx < (unsigned)WW)
            v = zb[gy*WW + gx];
        sm[sy][sx] = v;
    }
    float wk[9];
#pragma unroll
    for (int k = 0; k < 9; k++) wk[k] = w[c*9 + k];
    float g0 = g_gates[n*3+0], g1 = g_gates[n*3+1], g2 = g_gates[n*3+2];
    float bi = bias[c];
    __syncthreads();
    float lsum = 0.f, lsq = 0.f;
    float* yb = g_y + (size_t)nc * HW;
    for (int p = threadIdx.x; p < 28*28; p += 256) {
        int ty = p / 28, tx = p - ty*28;
        int cy = ty + 4, cx = tx + 4;
        float s1 = 0.f, s2 = 0.f, s4 = 0.f;
#pragma unroll
        for (int ky = 0; ky < 3; ky++)
#pragma unroll
            for (int kx = 0; kx < 3; kx++) {
                float wv = wk[ky*3 + kx];
                s1 += wv * sm[cy + (ky-1)    ][cx + (kx-1)    ];
                s2 += wv * sm[cy + 2*(ky-1)  ][cx + 2*(kx-1)  ];
                s4 += wv * sm[cy + 4*(ky-1)  ][cx + 4*(kx-1)  ];
            }
        float acc = bi + g0*s1 + g1*s2 + g2*s4;
        yb[(ty0 + ty)*WW + tx0 + tx] = acc;
        lsum += acc;
        lsq  += acc * acc;
    }
    red[threadIdx.x] = lsum;
    redq[threadIdx.x] = lsq;
    __syncthreads();
    for (int o = 128; o > 0; o >>= 1) {
        if (threadIdx.x < o) {
            red[threadIdx.x]  += red[threadIdx.x + o];
            redq[threadIdx.x] += redq[threadIdx.x + o];
        }
        __syncthreads();
    }
    if (threadIdx.x == 0) {
        atomicAdd(&g_sum[nc], red[0]);
        atomicAdd(&g_sumsq[nc], redq[0]);
    }
}

// ================= finalize IS-norm stats =================
__global__ void statsfin_kernel(const float* __restrict__ gamma, int t) {
    int i = threadIdx.x;  // 1024
    float mean = g_sum[i] * (1.f / (float)HW);
    float var  = g_sumsq[i] * (1.f / (float)HW) - mean*mean;
    float rstd = rsqrtf(var + 1e-5f);
    g_sum[i]   = mean;
    g_sumsq[i] = rstd * gamma[t*CH + (i & 127)];
}

// ================= normalize + ReLU6 + residual =================
__global__ void resid_kernel(float* __restrict__ h, const float* __restrict__ beta, int t) {
    int idx = blockIdx.x * 256 + threadIdx.x;  // [0, TOT/4)
    int nc = idx / (HW/4);
    int c = nc & 127;
    float mean = g_sum[nc], sc = g_sumsq[nc], bt = beta[t*CH + c];
    float4 y  = ((const float4*)g_y)[idx];
    float4 hv = ((float4*)h)[idx];
    float v;
    v = (y.x - mean)*sc + bt; v = fminf(fmaxf(v, 0.f), 6.f); hv.x += v;
    v = (y.y - mean)*sc + bt; v = fminf(fmaxf(v, 0.f), 6.f); hv.y += v;
    v = (y.z - mean)*sc + bt; v = fminf(fmaxf(v, 0.f), 6.f); hv.z += v;
    v = (y.w - mean)*sc + bt; v = fminf(fmaxf(v, 0.f), 6.f); hv.w += v;
    ((float4*)h)[idx] = hv;
}

extern "C" void kernel_launch(void* const* d_in, const int* in_sizes, int n_in,
                              void* d_out, int out_size) {
    const float* x     = (const float*)d_in[0];
    const float* dw_w  = (const float*)d_in[1];
    const float* dw_b  = (const float*)d_in[2];
    const float* sym_w = (const float*)d_in[3];
    const float* sym_b = (const float*)d_in[4];
    const float* gW    = (const float*)d_in[5];
    const float* gb    = (const float*)d_in[6];
    const float* gwe   = (const float*)d_in[7];
    const float* gamma = (const float*)d_in[8];
    const float* beta  = (const float*)d_in[9];
    float* h = (float*)d_out;

    copy_kernel<<<TOT/4/256, 256>>>(x, h);
    wsym_kernel<<<CH*CH/256, 256>>>(sym_w);

    for (int t = 0; t < 4; t++) {
        clear_kernel<<<1, 1024>>>();
        gap_kernel<<<NC, 256>>>(h);
        ent_kernel<<<(NB*NPOOL)/8, 256>>>(h);
        gate_kernel<<<1, 32>>>(gW, gb, gwe);
        symconv_kernel<<<dim3(HW/128, NB), 256>>>(h, sym_b);
        dw_kernel<<<dim3(16, NC), 256>>>(dw_w, dw_b);
        statsfin_kernel<<<1, 1024>>>(gamma, t);
        resid_kernel<<<TOT/4/256, 256>>>(h, beta, t);
    }
}

// round 6
// speedup vs baseline: 1.2839x; 1.2839x over previous
#include <cuda_runtime.h>
#include <math.h>
#include <stdint.h>

#define NB 8
#define CH 128
#define HH 112
#define WW 112
#define HW (HH*WW)          // 12544
#define NC (NB*CH)          // 1024
#define TOT (NB*CH*HW)      // 12,845,056
#define PP 37               // pooled dim (112/3)
#define NPOOL (PP*PP)       // 1369

// ---- scratch (device globals; no allocation in kernel_launch) ----
__device__ float g_z[TOT];      // sym-conv output
__device__ float g_y[TOT];      // dwconv output
__device__ float g_wsym[CH*CH]; // tf32-rounded symmetric weight
__device__ float g_gap[NC];
__device__ float g_ent[NB];
__device__ float g_gates[NB*3];
__device__ float g_sum[NC];     // later: mean
__device__ float g_sumsq[NC];   // later: rstd*gamma

__device__ __forceinline__ uint32_t tf32r(float x) {
    uint32_t u;
    asm("cvt.rna.tf32.f32 %0, %1;" : "=r"(u) : "f"(x));
    return u;
}
__device__ __forceinline__ void mma8(float* c, const uint32_t* a, const uint32_t* b) {
    asm volatile(
        "mma.sync.aligned.m16n8k8.row.col.f32.tf32.tf32.f32 "
        "{%0,%1,%2,%3}, {%4,%5,%6,%7}, {%8,%9}, {%0,%1,%2,%3};"
        : "+f"(c[0]), "+f"(c[1]), "+f"(c[2]), "+f"(c[3])
        : "r"(a[0]), "r"(a[1]), "r"(a[2]), "r"(a[3]), "r"(b[0]), "r"(b[1]));
}

// ================= copy x -> h, fused GAP for iter 0 =================
__global__ void copy_gap_kernel(const float* __restrict__ x, float* __restrict__ h) {
    int nc = blockIdx.x;
    const float4* xp = (const float4*)(x + (size_t)nc * HW);
    float4* hp = (float4*)(h + (size_t)nc * HW);
    float s = 0.f;
    for (int i = threadIdx.x; i < HW/4; i += 256) {
        float4 v = xp[i];
        hp[i] = v;
        s += (v.x + v.y) + (v.z + v.w);
    }
    __shared__ float red[256];
    red[threadIdx.x] = s;
    __syncthreads();
    for (int o = 128; o > 0; o >>= 1) {
        if (threadIdx.x < o) red[threadIdx.x] += red[threadIdx.x + o];
        __syncthreads();
    }
    if (threadIdx.x == 0) g_gap[nc] = red[0] * (1.f / (float)HW);
}

// ================= symmetrize W (+ tf32 rounding) =================
__global__ void wsym_kernel(const float* __restrict__ W) {
    int i = blockIdx.x * 256 + threadIdx.x;   // 16384
    int d = i >> 7, c = i & 127;
    uint32_t u = tf32r(0.5f * (W[d*CH + c] + W[c*CH + d]));
    g_wsym[i] = __uint_as_float(u);
}

// ================= clear accumulators =================
__global__ void clear_kernel() {
    int i = threadIdx.x;  // 1024
    if (i < NB) g_ent[i] = 0.f;
    g_sum[i] = 0.f;
    g_sumsq[i] = 0.f;
}

// ================= entropy over pooled channel-softmax =================
__global__ void ent_kernel(const float* __restrict__ h) {
    int warp = (blockIdx.x * blockDim.x + threadIdx.x) >> 5;  // [0, NB*NPOOL)
    int lane = threadIdx.x & 31;
    int n   = warp / NPOOL;
    int rem = warp - n * NPOOL;
    int py = rem / PP, px = rem - py * PP;
    const float* base = h + (size_t)n * CH * HW + (py*3) * WW + px*3;
    float v[4];
#pragma unroll
    for (int j = 0; j < 4; j++) {
        int c = j*32 + lane;
        const float* p = base + (size_t)c * HW;
        float s = 0.f;
#pragma unroll
        for (int r = 0; r < 3; r++) s += p[r*WW] + p[r*WW+1] + p[r*WW+2];
        v[j] = s * (1.f/9.f);
    }
    float m = fmaxf(fmaxf(v[0], v[1]), fmaxf(v[2], v[3]));
#pragma unroll
    for (int o = 16; o > 0; o >>= 1) m = fmaxf(m, __shfl_xor_sync(0xffffffffu, m, o));
    float s = 0.f;
#pragma unroll
    for (int j = 0; j < 4; j++) s += expf(v[j] - m);
#pragma unroll
    for (int o = 16; o > 0; o >>= 1) s += __shfl_xor_sync(0xffffffffu, s, o);
    float lse = m + logf(s);
    float e = 0.f;
#pragma unroll
    for (int j = 0; j < 4; j++) {
        float lp = v[j] - lse;
        e -= expf(lp) * lp;
    }
#pragma unroll
    for (int o = 16; o > 0; o >>= 1) e += __shfl_xor_sync(0xffffffffu, e, o);
    if (lane == 0) atomicAdd(&g_ent[n], e);
}

// ================= gate logits + softmax =================
__global__ void gate_kernel(const float* __restrict__ gW, const float* __restrict__ gb,
                            const float* __restrict__ gwe) {
    __shared__ float lg[NB][3];
    int t = threadIdx.x;  // 32 threads
    if (t < NB*3) {
        int n = t / 3, i = t - n*3;
        float s = 0.f;
        for (int c = 0; c < CH; c++) s += g_gap[n*CH + c] * gW[c*3 + i];
        float ent = g_ent[n] * (1.f / (float)NPOOL);
        lg[n][i] = s + gb[i] + ent * gwe[i];
    }
    __syncwarp();
    if (t < NB) {
        float a = lg[t][0], b = lg[t][1], c = lg[t][2];
        float m = fmaxf(a, fmaxf(b, c));
        float e0 = expf(a-m), e1 = expf(b-m), e2 = expf(c-m);
        float inv = 1.f / (e0 + e1 + e2);
        g_gates[t*3+0] = e0*inv;
        g_gates[t*3+1] = e1*inv;
        g_gates[t*3+2] = e2*inv;
    }
}

// ============ symmetric 1x1 conv via mma.sync tf32 ============
// Per CTA: z[:, p0..p0+127] for one n. M=128(outC) x N=128(pix) x K=128(inC).
// 8 warps, each 32(M) x 64(N). A = Wsym[m][k], B = h^T[pix][k], both smem stride 132.
#define AST 132
#define SYM_SMEM (2 * 128 * AST * 4)   // 135168 bytes

__global__ void __launch_bounds__(256) symconv_mma(const float* __restrict__ h,
                                                   const float* __restrict__ bias) {
    extern __shared__ float sm[];
    float* As = sm;                 // [m][k]  128 x AST
    float* Bs = sm + 128 * AST;     // [pix][k] 128 x AST
    int tid = threadIdx.x, lane = tid & 31, wid = tid >> 5;
    int n = blockIdx.y, p0 = blockIdx.x * 128;

    // fill A (g_wsym already tf32-rounded)
    for (int idx = tid; idx < 4096; idx += 256) {
        int m = idx >> 5, k4 = (idx & 31) << 2;
        float4 v = *(const float4*)&g_wsym[m*CH + k4];
        *(float4*)&As[m*AST + k4] = v;
    }
    // fill B: h[k][p0+pix] -> Bs[pix][k], tf32-rounded; global reads coalesced over pix
    const float* hb = h + (size_t)n * CH * HW + p0;
    for (int idx = tid; idx < 4096; idx += 256) {
        int pix = idx & 127, k4 = (idx >> 7) << 2;
        float* dst = &Bs[pix*AST + k4];
        dst[0] = __uint_as_float(tf32r(hb[(size_t)(k4+0) * HW + pix]));
        dst[1] = __uint_as_float(tf32r(hb[(size_t)(k4+1) * HW + pix]));
        dst[2] = __uint_as_float(tf32r(hb[(size_t)(k4+2) * HW + pix]));
        dst[3] = __uint_as_float(tf32r(hb[(size_t)(k4+3) * HW + pix]));
    }
    __syncthreads();

    int m0 = (wid & 3) * 32;     // warp M offset
    int n0 = (wid >> 2) * 64;    // warp N offset
    int gr = lane >> 2, tg = lane & 3;

    float acc[2][8][4];
#pragma unroll
    for (int i = 0; i < 2; i++)
#pragma unroll
        for (int j = 0; j < 8; j++)
#pragma unroll
            for (int r = 0; r < 4; r++) acc[i][j][r] = 0.f;

#pragma unroll
    for (int ks = 0; ks < 16; ks++) {
        int k0 = ks * 8;
        uint32_t a[2][4], b[8][2];
#pragma unroll
        for (int i = 0; i < 2; i++) {
            const float* ap = &As[(m0 + i*16 + gr)*AST + k0 + tg];
            a[i][0] = __float_as_uint(ap[0]);
            a[i][1] = __float_as_uint(ap[8*AST]);
            a[i][2] = __float_as_uint(ap[4]);
            a[i][3] = __float_as_uint(ap[8*AST + 4]);
        }
#pragma unroll
        for (int j = 0; j < 8; j++) {
            const float* bp = &Bs[(n0 + j*8 + gr)*AST + k0 + tg];
            b[j][0] = __float_as_uint(bp[0]);
            b[j][1] = __float_as_uint(bp[4]);
        }
#pragma unroll
        for (int i = 0; i < 2; i++)
#pragma unroll
            for (int j = 0; j < 8; j++)
                mma8(acc[i][j], a[i], b[j]);
    }

    // epilogue: c0,c1 -> (row, 2*tg + n0 + 8j), c2,c3 -> row+8
    float* zb = g_z + (size_t)n * CH * HW + p0;
#pragma unroll
    for (int i = 0; i < 2; i++) {
        int r0 = m0 + i*16 + gr;
        float bi0 = bias[r0], bi1 = bias[r0 + 8];
#pragma unroll
        for (int j = 0; j < 8; j++) {
            int col = n0 + j*8 + tg*2;
            float2 v0 = make_float2(acc[i][j][0] + bi0, acc[i][j][1] + bi0);
            float2 v1 = make_float2(acc[i][j][2] + bi1, acc[i][j][3] + bi1);
            *(float2*)&zb[(size_t)r0       * HW + col] = v0;
            *(float2*)&zb[(size_t)(r0 + 8) * HW + col] = v1;
        }
    }
}

// ================= gated tri-dilated depthwise conv + IS-norm stats =================
__global__ void __launch_bounds__(256) dw_kernel(const float* __restrict__ w,
                                                 const float* __restrict__ bias) {
    int nc = blockIdx.y;
    int n = nc >> 7, c = nc & 127;
    int ty0 = (blockIdx.x >> 2) * 28, tx0 = (blockIdx.x & 3) * 28;
    __shared__ float sm[36][36];
    __shared__ float red[256];
    __shared__ float redq[256];
    const float* zb = g_z + (size_t)nc * HW;
    for (int s = threadIdx.x; s < 36*36; s += 256) {
        int sy = s / 36, sx = s - sy*36;
        int gy = ty0 - 4 + sy, gx = tx0 - 4 + sx;
        float v = 0.f;
        if ((unsigned)gy < (unsigned)HH && (unsigned)gx < (unsigned)WW)
            v = zb[gy*WW + gx];
        sm[sy][sx] = v;
    }
    float wk[9];
#pragma unroll
    for (int k = 0; k < 9; k++) wk[k] = w[c*9 + k];
    float g0 = g_gates[n*3+0], g1 = g_gates[n*3+1], g2 = g_gates[n*3+2];
    float bi = bias[c];
    __syncthreads();
    float lsum = 0.f, lsq = 0.f;
    float* yb = g_y + (size_t)nc * HW;
    for (int p = threadIdx.x; p < 28*28; p += 256) {
        int ty = p / 28, tx = p - ty*28;
        int cy = ty + 4, cx = tx + 4;
        float s1 = 0.f, s2 = 0.f, s4 = 0.f;
#pragma unroll
        for (int ky = 0; ky < 3; ky++)
#pragma unroll
            for (int kx = 0; kx < 3; kx++) {
                float wv = wk[ky*3 + kx];
                s1 += wv * sm[cy + (ky-1)    ][cx + (kx-1)    ];
                s2 += wv * sm[cy + 2*(ky-1)  ][cx + 2*(kx-1)  ];
                s4 += wv * sm[cy + 4*(ky-1)  ][cx + 4*(kx-1)  ];
            }
        float acc = bi + g0*s1 + g1*s2 + g2*s4;
        yb[(ty0 + ty)*WW + tx0 + tx] = acc;
        lsum += acc;
        lsq  += acc * acc;
    }
    red[threadIdx.x] = lsum;
    redq[threadIdx.x] = lsq;
    __syncthreads();
    for (int o = 128; o > 0; o >>= 1) {
        if (threadIdx.x < o) {
            red[threadIdx.x]  += red[threadIdx.x + o];
            redq[threadIdx.x] += redq[threadIdx.x + o];
        }
        __syncthreads();
    }
    if (threadIdx.x == 0) {
        atomicAdd(&g_sum[nc], red[0]);
        atomicAdd(&g_sumsq[nc], redq[0]);
    }
}

// ================= finalize IS-norm stats =================
__global__ void statsfin_kernel(const float* __restrict__ gamma, int t) {
    int i = threadIdx.x;  // 1024
    float mean = g_sum[i] * (1.f / (float)HW);
    float var  = g_sumsq[i] * (1.f / (float)HW) - mean*mean;
    float rstd = rsqrtf(var + 1e-5f);
    g_sum[i]   = mean;
    g_sumsq[i] = rstd * gamma[t*CH + (i & 127)];
}

// ================= normalize + ReLU6 + residual, fused GAP for next iter =================
__global__ void __launch_bounds__(256) resid_kernel(float* __restrict__ h,
                                                    const float* __restrict__ beta, int t) {
    int nc = blockIdx.x;
    int c = nc & 127;
    float mean = g_sum[nc], sc = g_sumsq[nc], bt = beta[t*CH + c];
    const float4* yp = (const float4*)(g_y + (size_t)nc * HW);
    float4* hp = (float4*)(h + (size_t)nc * HW);
    float s = 0.f;
    for (int i = threadIdx.x; i < HW/4; i += 256) {
        float4 y = yp[i];
        float4 hv = hp[i];
        float v;
        v = (y.x - mean)*sc + bt; v = fminf(fmaxf(v, 0.f), 6.f); hv.x += v;
        v = (y.y - mean)*sc + bt; v = fminf(fmaxf(v, 0.f), 6.f); hv.y += v;
        v = (y.z - mean)*sc + bt; v = fminf(fmaxf(v, 0.f), 6.f); hv.z += v;
        v = (y.w - mean)*sc + bt; v = fminf(fmaxf(v, 0.f), 6.f); hv.w += v;
        hp[i] = hv;
        s += (hv.x + hv.y) + (hv.z + hv.w);
    }
    __shared__ float red[256];
    red[threadIdx.x] = s;
    __syncthreads();
    for (int o = 128; o > 0; o >>= 1) {
        if (threadIdx.x < o) red[threadIdx.x] += red[threadIdx.x + o];
        __syncthreads();
    }
    if (threadIdx.x == 0) g_gap[nc] = red[0] * (1.f / (float)HW);
}

extern "C" void kernel_launch(void* const* d_in, const int* in_sizes, int n_in,
                              void* d_out, int out_size) {
    const float* x     = (const float*)d_in[0];
    const float* dw_w  = (const float*)d_in[1];
    const float* dw_b  = (const float*)d_in[2];
    const float* sym_w = (const float*)d_in[3];
    const float* sym_b = (const float*)d_in[4];
    const float* gW    = (const float*)d_in[5];
    const float* gb    = (const float*)d_in[6];
    const float* gwe   = (const float*)d_in[7];
    const float* gamma = (const float*)d_in[8];
    const float* beta  = (const float*)d_in[9];
    float* h = (float*)d_out;

    cudaFuncSetAttribute(symconv_mma, cudaFuncAttributeMaxDynamicSharedMemorySize, SYM_SMEM);

    copy_gap_kernel<<<NC, 256>>>(x, h);
    wsym_kernel<<<CH*CH/256, 256>>>(sym_w);

    for (int t = 0; t < 4; t++) {
        clear_kernel<<<1, 1024>>>();
        ent_kernel<<<(NB*NPOOL)/8, 256>>>(h);
        gate_kernel<<<1, 32>>>(gW, gb, gwe);
        symconv_mma<<<dim3(HW/128, NB), 256, SYM_SMEM>>>(h, sym_b);
        dw_kernel<<<dim3(16, NC), 256>>>(dw_w, dw_b);
        statsfin_kernel<<<1, 1024>>>(gamma, t);
        resid_kernel<<<NC, 256>>>(h, beta, t);
    }
}

// round 8
// speedup vs baseline: 1.7467x; 1.3604x over previous
#include <cuda_runtime.h>
#include <math.h>
#include <stdint.h>

#define NB 8
#define CH 128
#define HH 112
#define WW 112
#define HW (HH*WW)          // 12544
#define NC (NB*CH)          // 1024
#define TOT (NB*CH*HW)      // 12,845,056
#define PP 37               // pooled dim (112/3)
#define NPOOL (PP*PP)       // 1369

// ---- scratch (device globals; no allocation in kernel_launch) ----
__device__ float g_z[TOT];      // sym-conv output
__device__ float g_y[TOT];      // dwconv output
__device__ float g_wsym[CH*CH]; // tf32-rounded symmetric weight
__device__ float g_gap[NC];
__device__ float g_ent[NB];
__device__ float g_gates[NB*3];
__device__ float g_sum[NC];     // later: mean
__device__ float g_sumsq[NC];   // later: rstd*gamma

__device__ __forceinline__ uint32_t tf32r(float x) {
    uint32_t u;
    asm("cvt.rna.tf32.f32 %0, %1;" : "=r"(u) : "f"(x));
    return u;
}
__device__ __forceinline__ void mma8(float* c, const uint32_t* a, const uint32_t* b) {
    asm volatile(
        "mma.sync.aligned.m16n8k8.row.col.f32.tf32.tf32.f32 "
        "{%0,%1,%2,%3}, {%4,%5,%6,%7}, {%8,%9}, {%0,%1,%2,%3};"
        : "+f"(c[0]), "+f"(c[1]), "+f"(c[2]), "+f"(c[3])
        : "r"(a[0]), "r"(a[1]), "r"(a[2]), "r"(a[3]), "r"(b[0]), "r"(b[1]));
}

// ================= copy x -> h, fused GAP for iter 0 =================
__global__ void copy_gap_kernel(const float* __restrict__ x, float* __restrict__ h) {
    int nc = blockIdx.x;
    const float4* xp = (const float4*)(x + (size_t)nc * HW);
    float4* hp = (float4*)(h + (size_t)nc * HW);
    float s = 0.f;
    for (int i = threadIdx.x; i < HW/4; i += 256) {
        float4 v = xp[i];
        hp[i] = v;
        s += (v.x + v.y) + (v.z + v.w);
    }
    __shared__ float red[256];
    red[threadIdx.x] = s;
    __syncthreads();
    for (int o = 128; o > 0; o >>= 1) {
        if (threadIdx.x < o) red[threadIdx.x] += red[threadIdx.x + o];
        __syncthreads();
    }
    if (threadIdx.x == 0) g_gap[nc] = red[0] * (1.f / (float)HW);
}

// ================= symmetrize W (+ tf32 rounding) =================
__global__ void wsym_kernel(const float* __restrict__ W) {
    int i = blockIdx.x * 256 + threadIdx.x;   // 16384
    int d = i >> 7, c = i & 127;
    uint32_t u = tf32r(0.5f * (W[d*CH + c] + W[c*CH + d]));
    g_wsym[i] = __uint_as_float(u);
}

// ================= clear accumulators (once, before the loop) =================
__global__ void clear_kernel() {
    int i = threadIdx.x;  // 1024
    if (i < NB) g_ent[i] = 0.f;
    g_sum[i] = 0.f;
    g_sumsq[i] = 0.f;
}

// ================= entropy: block per (n, pooled-row) =================
// Phase 1: pooled[c][px] into smem with x-contiguous access. Phase 2: softmax-entropy.
__global__ void __launch_bounds__(256) ent_kernel(const float* __restrict__ h) {
    __shared__ float pooled[CH][41];   // pad 41: phase-2 lane stride 41 (coprime 32)
    __shared__ float er[8];
    int n = blockIdx.x / PP;
    int py = blockIdx.x - n * PP;
    int tid = threadIdx.x, wid = tid >> 5, lane = tid & 31;
    const float* hn = h + (size_t)n * CH * HW + (3*py) * WW;

    // phase 1: 128*37 = 4736 work items
    for (int idx = tid; idx < CH * PP; idx += 256) {
        int c = idx / PP, px = idx - c * PP;
        const float* p = hn + (size_t)c * HW + 3*px;
        float s = 0.f;
#pragma unroll
        for (int r = 0; r < 3; r++) s += p[r*WW] + p[r*WW+1] + p[r*WW+2];
        pooled[c][px] = s * (1.f/9.f);
    }
    __syncthreads();

    // phase 2: warps stride over px columns
    float esum = 0.f;
    for (int px = wid; px < PP; px += 8) {
        float v[4];
#pragma unroll
        for (int j = 0; j < 4; j++) v[j] = pooled[j*32 + lane][px];
        float m = fmaxf(fmaxf(v[0], v[1]), fmaxf(v[2], v[3]));
#pragma unroll
        for (int o = 16; o > 0; o >>= 1) m = fmaxf(m, __shfl_xor_sync(0xffffffffu, m, o));
        float s = 0.f;
#pragma unroll
        for (int j = 0; j < 4; j++) s += expf(v[j] - m);
#pragma unroll
        for (int o = 16; o > 0; o >>= 1) s += __shfl_xor_sync(0xffffffffu, s, o);
        float lse = m + logf(s);
        float e = 0.f;
#pragma unroll
        for (int j = 0; j < 4; j++) {
            float lp = v[j] - lse;
            e -= expf(lp) * lp;
        }
#pragma unroll
        for (int o = 16; o > 0; o >>= 1) e += __shfl_xor_sync(0xffffffffu, e, o);
        if (lane == 0) esum += e;
    }
    if (lane == 0) er[wid] = esum;
    __syncthreads();
    if (tid == 0) {
        float t = 0.f;
#pragma unroll
        for (int i = 0; i < 8; i++) t += er[i];
        atomicAdd(&g_ent[n], t);
    }
}

// ================= gate logits + softmax =================
__global__ void gate_kernel(const float* __restrict__ gW, const float* __restrict__ gb,
                            const float* __restrict__ gwe) {
    __shared__ float lg[NB][3];
    int t = threadIdx.x;  // 32 threads
    if (t < NB*3) {
        int n = t / 3, i = t - n*3;
        float s = 0.f;
        for (int c = 0; c < CH; c++) s += g_gap[n*CH + c] * gW[c*3 + i];
        float ent = g_ent[n] * (1.f / (float)NPOOL);
        lg[n][i] = s + gb[i] + ent * gwe[i];
    }
    __syncwarp();
    if (t < NB) {
        float a = lg[t][0], b = lg[t][1], c = lg[t][2];
        float m = fmaxf(a, fmaxf(b, c));
        float e0 = expf(a-m), e1 = expf(b-m), e2 = expf(c-m);
        float inv = 1.f / (e0 + e1 + e2);
        g_gates[t*3+0] = e0*inv;
        g_gates[t*3+1] = e1*inv;
        g_gates[t*3+2] = e2*inv;
    }
}

// ============ symmetric 1x1 conv via mma.sync tf32 ============
#define AST 132
#define SYM_SMEM (2 * 128 * AST * 4)   // 135168 bytes

__global__ void __launch_bounds__(256) symconv_mma(const float* __restrict__ h,
                                                   const float* __restrict__ bias) {
    extern __shared__ float sm[];
    float* As = sm;                 // [m][k]  128 x AST
    float* Bs = sm + 128 * AST;     // [pix][k] 128 x AST
    int tid = threadIdx.x, lane = tid & 31, wid = tid >> 5;
    int n = blockIdx.y, p0 = blockIdx.x * 128;

    for (int idx = tid; idx < 4096; idx += 256) {
        int m = idx >> 5, k4 = (idx & 31) << 2;
        float4 v = *(const float4*)&g_wsym[m*CH + k4];
        *(float4*)&As[m*AST + k4] = v;
    }
    const float* hb = h + (size_t)n * CH * HW + p0;
    for (int idx = tid; idx < 4096; idx += 256) {
        int pix = idx & 127, k4 = (idx >> 7) << 2;
        float* dst = &Bs[pix*AST + k4];
        dst[0] = __uint_as_float(tf32r(hb[(size_t)(k4+0) * HW + pix]));
        dst[1] = __uint_as_float(tf32r(hb[(size_t)(k4+1) * HW + pix]));
        dst[2] = __uint_as_float(tf32r(hb[(size_t)(k4+2) * HW + pix]));
        dst[3] = __uint_as_float(tf32r(hb[(size_t)(k4+3) * HW + pix]));
    }
    __syncthreads();

    int m0 = (wid & 3) * 32;
    int n0 = (wid >> 2) * 64;
    int gr = lane >> 2, tg = lane & 3;

    float acc[2][8][4];
#pragma unroll
    for (int i = 0; i < 2; i++)
#pragma unroll
        for (int j = 0; j < 8; j++)
#pragma unroll
            for (int r = 0; r < 4; r++) acc[i][j][r] = 0.f;

#pragma unroll
    for (int ks = 0; ks < 16; ks++) {
        int k0 = ks * 8;
        uint32_t a[2][4], b[8][2];
#pragma unroll
        for (int i = 0; i < 2; i++) {
            const float* ap = &As[(m0 + i*16 + gr)*AST + k0 + tg];
            a[i][0] = __float_as_uint(ap[0]);
            a[i][1] = __float_as_uint(ap[8*AST]);
            a[i][2] = __float_as_uint(ap[4]);
            a[i][3] = __float_as_uint(ap[8*AST + 4]);
        }
#pragma unroll
        for (int j = 0; j < 8; j++) {
            const float* bp = &Bs[(n0 + j*8 + gr)*AST + k0 + tg];
            b[j][0] = __float_as_uint(bp[0]);
            b[j][1] = __float_as_uint(bp[4]);
        }
#pragma unroll
        for (int i = 0; i < 2; i++)
#pragma unroll
            for (int j = 0; j < 8; j++)
                mma8(acc[i][j], a[i], b[j]);
    }

    float* zb = g_z + (size_t)n * CH * HW + p0;
#pragma unroll
    for (int i = 0; i < 2; i++) {
        int r0 = m0 + i*16 + gr;
        float bi0 = bias[r0], bi1 = bias[r0 + 8];
#pragma unroll
        for (int j = 0; j < 8; j++) {
            int col = n0 + j*8 + tg*2;
            float2 v0 = make_float2(acc[i][j][0] + bi0, acc[i][j][1] + bi0);
            float2 v1 = make_float2(acc[i][j][2] + bi1, acc[i][j][3] + bi1);
            *(float2*)&zb[(size_t)r0       * HW + col] = v0;
            *(float2*)&zb[(size_t)(r0 + 8) * HW + col] = v1;
        }
    }
}

// ======== gated tri-dilated depthwise conv + IS-norm stats (56x56 tiles) ========
__global__ void __launch_bounds__(256) dw_kernel(const float* __restrict__ w,
                                                 const float* __restrict__ bias) {
    int nc = blockIdx.y;
    int n = nc >> 7, c = nc & 127;
    int ty0 = (blockIdx.x >> 1) * 56, tx0 = (blockIdx.x & 1) * 56;
    __shared__ float sm[64][64];
    __shared__ float red[256];
    __shared__ float redq[256];
    const float* zb = g_z + (size_t)nc * HW;
    for (int s = threadIdx.x; s < 64*64; s += 256) {
        int sy = s >> 6, sx = s & 63;
        int gy = ty0 - 4 + sy, gx = tx0 - 4 + sx;
        float v = 0.f;
        if ((unsigned)gy < (unsigned)HH && (unsigned)gx < (unsigned)WW)
            v = zb[gy*WW + gx];
        sm[sy][sx] = v;
    }
    float wk[9];
#pragma unroll
    for (int k = 0; k < 9; k++) wk[k] = w[c*9 + k];
    float g0 = g_gates[n*3+0], g1 = g_gates[n*3+1], g2 = g_gates[n*3+2];
    float bi = bias[c];
    __syncthreads();
    float lsum = 0.f, lsq = 0.f;
    float* yb = g_y + (size_t)nc * HW;
    for (int p = threadIdx.x; p < 56*56; p += 256) {
        int ty = p / 56, tx = p - ty*56;
        int cy = ty + 4, cx = tx + 4;
        float s1 = 0.f, s2 = 0.f, s4 = 0.f;
#pragma unroll
        for (int ky = 0; ky < 3; ky++)
#pragma unroll
            for (int kx = 0; kx < 3; kx++) {
                float wv = wk[ky*3 + kx];
                s1 += wv * sm[cy + (ky-1)    ][cx + (kx-1)    ];
                s2 += wv * sm[cy + 2*(ky-1)  ][cx + 2*(kx-1)  ];
                s4 += wv * sm[cy + 4*(ky-1)  ][cx + 4*(kx-1)  ];
            }
        float acc = bi + g0*s1 + g1*s2 + g2*s4;
        yb[(ty0 + ty)*WW + tx0 + tx] = acc;
        lsum += acc;
        lsq  += acc * acc;
    }
    red[threadIdx.x] = lsum;
    redq[threadIdx.x] = lsq;
    __syncthreads();
    for (int o = 128; o > 0; o >>= 1) {
        if (threadIdx.x < o) {
            red[threadIdx.x]  += red[threadIdx.x + o];
            redq[threadIdx.x] += redq[threadIdx.x + o];
        }
        __syncthreads();
    }
    if (threadIdx.x == 0) {
        atomicAdd(&g_sum[nc], red[0]);
        atomicAdd(&g_sumsq[nc], redq[0]);
    }
}

// ================= finalize IS-norm stats =================
__global__ void statsfin_kernel(const float* __restrict__ gamma, int t) {
    int i = threadIdx.x;  // 1024
    float mean = g_sum[i] * (1.f / (float)HW);
    float var  = g_sumsq[i] * (1.f / (float)HW) - mean*mean;
    float rstd = rsqrtf(var + 1e-5f);
    g_sum[i]   = mean;
    g_sumsq[i] = rstd * gamma[t*CH + (i & 127)];
}

// ======= normalize + ReLU6 + residual, fused GAP + accumulator re-clear =======
__global__ void __launch_bounds__(256) resid_kernel(float* __restrict__ h,
                                                    const float* __restrict__ beta, int t) {
    int nc = blockIdx.x;
    int c = nc & 127;
    float mean = g_sum[nc], sc = g_sumsq[nc], bt = beta[t*CH + c];
    const float4* yp = (const float4*)(g_y + (size_t)nc * HW);
    float4* hp = (float4*)(h + (size_t)nc * HW);
    float s = 0.f;
    for (int i = threadIdx.x; i < HW/4; i += 256) {
        float4 y = yp[i];
        float4 hv = hp[i];
        float v;
        v = (y.x - mean)*sc + bt; v = fminf(fmaxf(v, 0.f), 6.f); hv.x += v;
        v = (y.y - mean)*sc + bt; v = fminf(fmaxf(v, 0.f), 6.f); hv.y += v;
        v = (y.z - mean)*sc + bt; v = fminf(fmaxf(v, 0.f), 6.f); hv.z += v;
        v = (y.w - mean)*sc + bt; v = fminf(fmaxf(v, 0.f), 6.f); hv.w += v;
        hp[i] = hv;
        s += (hv.x + hv.y) + (hv.z + hv.w);
    }
    __shared__ float red[256];
    red[threadIdx.x] = s;
    __syncthreads();
    for (int o = 128; o > 0; o >>= 1) {
        if (threadIdx.x < o) red[threadIdx.x] += red[threadIdx.x + o];
        __syncthreads();
    }
    if (threadIdx.x == 0) {
        g_gap[nc] = red[0] * (1.f / (float)HW);
        // re-arm accumulators for next iteration (reads happened before barrier)
        g_sum[nc] = 0.f;
        g_sumsq[nc] = 0.f;
        if (nc < NB) g_ent[nc] = 0.f;
    }
}

extern "C" void kernel_launch(void* const* d_in, const int* in_sizes, int n_in,
                              void* d_out, int out_size) {
    const float* x     = (const float*)d_in[0];
    const float* dw_w  = (const float*)d_in[1];
    const float* dw_b  = (const float*)d_in[2];
    const float* sym_w = (const float*)d_in[3];
    const float* sym_b = (const float*)d_in[4];
    const float* gW    = (const float*)d_in[5];
    const float* gb    = (const float*)d_in[6];
    const float* gwe   = (const float*)d_in[7];
    const float* gamma = (const float*)d_in[8];
    const float* beta  = (const float*)d_in[9];
    float* h = (float*)d_out;

    cudaFuncSetAttribute(symconv_mma, cudaFuncAttributeMaxDynamicSharedMemorySize, SYM_SMEM);

    copy_gap_kernel<<<NC, 256>>>(x, h);
    wsym_kernel<<<CH*CH/256, 256>>>(sym_w);
    clear_kernel<<<1, 1024>>>();

    for (int t = 0; t < 4; t++) {
        ent_kernel<<<NB*PP, 256>>>(h);
        gate_kernel<<<1, 32>>>(gW, gb, gwe);
        symconv_mma<<<dim3(HW/128, NB), 256, SYM_SMEM>>>(h, sym_b);
        dw_kernel<<<dim3(4, NC), 256>>>(dw_w, dw_b);
        statsfin_kernel<<<1, 1024>>>(gamma, t);
        resid_kernel<<<NC, 256>>>(h, beta, t);
    }
}

// round 10
// speedup vs baseline: 1.7501x; 1.0020x over previous
#include <cuda_runtime.h>
#include <math.h>
#include <stdint.h>

#define NB 8
#define CH 128
#define HH 112
#define WW 112
#define HW (HH*WW)          // 12544
#define NC (NB*CH)          // 1024
#define TOT (NB*CH*HW)      // 12,845,056
#define PP 37               // pooled dim (112/3)
#define NPOOL (PP*PP)       // 1369

// ---- scratch (device globals; no allocation in kernel_launch) ----
__device__ float g_z[TOT];      // sym-conv output
__device__ float g_wsym[CH*CH]; // tf32-rounded symmetric weight
__device__ float g_gap[NC];
__device__ float g_ent[NB];
__device__ float g_gates[NB*3];

__device__ __forceinline__ uint32_t tf32r(float x) {
    uint32_t u;
    asm("cvt.rna.tf32.f32 %0, %1;" : "=r"(u) : "f"(x));
    return u;
}
__device__ __forceinline__ void mma8(float* c, const uint32_t* a, const uint32_t* b) {
    asm volatile(
        "mma.sync.aligned.m16n8k8.row.col.f32.tf32.tf32.f32 "
        "{%0,%1,%2,%3}, {%4,%5,%6,%7}, {%8,%9}, {%0,%1,%2,%3};"
        : "+f"(c[0]), "+f"(c[1]), "+f"(c[2]), "+f"(c[3])
        : "r"(a[0]), "r"(a[1]), "r"(a[2]), "r"(a[3]), "r"(b[0]), "r"(b[1]));
}

// ================= copy x -> h, fused GAP for iter 0 =================
__global__ void copy_gap_kernel(const float* __restrict__ x, float* __restrict__ h) {
    int nc = blockIdx.x;
    const float4* xp = (const float4*)(x + (size_t)nc * HW);
    float4* hp = (float4*)(h + (size_t)nc * HW);
    float s = 0.f;
    for (int i = threadIdx.x; i < HW/4; i += 256) {
        float4 v = xp[i];
        hp[i] = v;
        s += (v.x + v.y) + (v.z + v.w);
    }
    __shared__ float red[256];
    red[threadIdx.x] = s;
    __syncthreads();
    for (int o = 128; o > 0; o >>= 1) {
        if (threadIdx.x < o) red[threadIdx.x] += red[threadIdx.x + o];
        __syncthreads();
    }
    if (threadIdx.x == 0) {
        g_gap[nc] = red[0] * (1.f / (float)HW);
        if (nc < NB) g_ent[nc] = 0.f;
    }
}

// ================= symmetrize W (+ tf32 rounding) =================
__global__ void wsym_kernel(const float* __restrict__ W) {
    int i = blockIdx.x * 256 + threadIdx.x;   // 16384
    int d = i >> 7, c = i & 127;
    uint32_t u = tf32r(0.5f * (W[d*CH + c] + W[c*CH + d]));
    g_wsym[i] = __uint_as_float(u);
}

// ================= entropy: block per (n, pooled-row, px-chunk) =================
#define EC 10   // px chunk width
#define ECN 4   // chunks per row (10,10,10,7)
__global__ void __launch_bounds__(256) ent_kernel(const float* __restrict__ h) {
    __shared__ float pooled[CH][EC+1];
    __shared__ float er[8];
    int b = blockIdx.x;
    int s = b & 3;
    int npy = b >> 2;
    int n = npy / PP;
    int py = npy - n * PP;
    int px0 = s * EC;
    int pw = min(EC, PP - px0);
    int tid = threadIdx.x, wid = tid >> 5, lane = tid & 31;
    const float* hn = h + (size_t)n * CH * HW + (3*py) * WW + 3*px0;

    for (int idx = tid; idx < CH * pw; idx += 256) {
        int c = idx / pw, px = idx - c * pw;
        const float* p = hn + (size_t)c * HW + 3*px;
        float v = 0.f;
#pragma unroll
        for (int r = 0; r < 3; r++) v += p[r*WW] + p[r*WW+1] + p[r*WW+2];
        pooled[c][px] = v * (1.f/9.f);
    }
    __syncthreads();

    float esum = 0.f;
    for (int px = wid; px < pw; px += 8) {
        float v[4];
#pragma unroll
        for (int j = 0; j < 4; j++) v[j] = pooled[j*32 + lane][px];
        float m = fmaxf(fmaxf(v[0], v[1]), fmaxf(v[2], v[3]));
#pragma unroll
        for (int o = 16; o > 0; o >>= 1) m = fmaxf(m, __shfl_xor_sync(0xffffffffu, m, o));
        float ss = 0.f;
#pragma unroll
        for (int j = 0; j < 4; j++) ss += expf(v[j] - m);
#pragma unroll
        for (int o = 16; o > 0; o >>= 1) ss += __shfl_xor_sync(0xffffffffu, ss, o);
        float lse = m + logf(ss);
        float e = 0.f;
#pragma unroll
        for (int j = 0; j < 4; j++) {
            float lp = v[j] - lse;
            e -= expf(lp) * lp;
        }
#pragma unroll
        for (int o = 16; o > 0; o >>= 1) e += __shfl_xor_sync(0xffffffffu, e, o);
        if (lane == 0) esum += e;
    }
    if (lane == 0) er[wid] = esum;
    __syncthreads();
    if (tid == 0) {
        float t = 0.f;
#pragma unroll
        for (int i = 0; i < 8; i++) t += er[i];
        atomicAdd(&g_ent[n], t);
    }
}

// ================= gate logits + softmax (re-arms g_ent) =================
__global__ void gate_kernel(const float* __restrict__ gW, const float* __restrict__ gb,
                            const float* __restrict__ gwe) {
    __shared__ float lg[NB][3];
    int t = threadIdx.x;  // 32 threads
    if (t < NB*3) {
        int n = t / 3, i = t - n*3;
        float s = 0.f;
        for (int c = 0; c < CH; c++) s += g_gap[n*CH + c] * gW[c*3 + i];
        float ent = g_ent[n] * (1.f / (float)NPOOL);
        lg[n][i] = s + gb[i] + ent * gwe[i];
    }
    __syncwarp();
    if (t < NB) {
        float a = lg[t][0], b = lg[t][1], c = lg[t][2];
        float m = fmaxf(a, fmaxf(b, c));
        float e0 = expf(a-m), e1 = expf(b-m), e2 = expf(c-m);
        float inv = 1.f / (e0 + e1 + e2);
        g_gates[t*3+0] = e0*inv;
        g_gates[t*3+1] = e1*inv;
        g_gates[t*3+2] = e2*inv;
        g_ent[t] = 0.f;   // re-arm for next iteration
    }
}

// ============ symmetric 1x1 conv via mma.sync tf32 ============
#define AST 132
#define SYM_SMEM (2 * 128 * AST * 4)   // 135168 bytes

__global__ void __launch_bounds__(256) symconv_mma(const float* __restrict__ h,
                                                   const float* __restrict__ bias) {
    extern __shared__ float sm[];
    float* As = sm;                 // [m][k]  128 x AST
    float* Bs = sm + 128 * AST;     // [pix][k] 128 x AST
    int tid = threadIdx.x, lane = tid & 31, wid = tid >> 5;
    int n = blockIdx.y, p0 = blockIdx.x * 128;

    for (int idx = tid; idx < 4096; idx += 256) {
        int m = idx >> 5, k4 = (idx & 31) << 2;
        float4 v = *(const float4*)&g_wsym[m*CH + k4];
        *(float4*)&As[m*AST + k4] = v;
    }
    const float* hb = h + (size_t)n * CH * HW + p0;
    for (int idx = tid; idx < 4096; idx += 256) {
        int pix = idx & 127, k4 = (idx >> 7) << 2;
        float* dst = &Bs[pix*AST + k4];
        dst[0] = __uint_as_float(tf32r(hb[(size_t)(k4+0) * HW + pix]));
        dst[1] = __uint_as_float(tf32r(hb[(size_t)(k4+1) * HW + pix]));
        dst[2] = __uint_as_float(tf32r(hb[(size_t)(k4+2) * HW + pix]));
        dst[3] = __uint_as_float(tf32r(hb[(size_t)(k4+3) * HW + pix]));
    }
    __syncthreads();

    int m0 = (wid & 3) * 32;
    int n0 = (wid >> 2) * 64;
    int gr = lane >> 2, tg = lane & 3;

    float acc[2][8][4];
#pragma unroll
    for (int i = 0; i < 2; i++)
#pragma unroll
        for (int j = 0; j < 8; j++)
#pragma unroll
            for (int r = 0; r < 4; r++) acc[i][j][r] = 0.f;

#pragma unroll
    for (int ks = 0; ks < 16; ks++) {
        int k0 = ks * 8;
        uint32_t a[2][4], b[8][2];
#pragma unroll
        for (int i = 0; i < 2; i++) {
            const float* ap = &As[(m0 + i*16 + gr)*AST + k0 + tg];
            a[i][0] = __float_as_uint(ap[0]);
            a[i][1] = __float_as_uint(ap[8*AST]);
            a[i][2] = __float_as_uint(ap[4]);
            a[i][3] = __float_as_uint(ap[8*AST + 4]);
        }
#pragma unroll
        for (int j = 0; j < 8; j++) {
            const float* bp = &Bs[(n0 + j*8 + gr)*AST + k0 + tg];
            b[j][0] = __float_as_uint(bp[0]);
            b[j][1] = __float_as_uint(bp[4]);
        }
#pragma unroll
        for (int i = 0; i < 2; i++)
#pragma unroll
            for (int j = 0; j < 8; j++)
                mma8(acc[i][j], a[i], b[j]);
    }

    float* zb = g_z + (size_t)n * CH * HW + p0;
#pragma unroll
    for (int i = 0; i < 2; i++) {
        int r0 = m0 + i*16 + gr;
        float bi0 = bias[r0], bi1 = bias[r0 + 8];
#pragma unroll
        for (int j = 0; j < 8; j++) {
            int col = n0 + j*8 + tg*2;
            float2 v0 = make_float2(acc[i][j][0] + bi0, acc[i][j][1] + bi0);
            float2 v1 = make_float2(acc[i][j][2] + bi1, acc[i][j][3] + bi1);
            *(float2*)&zb[(size_t)r0       * HW + col] = v0;
            *(float2*)&zb[(size_t)(r0 + 8) * HW + col] = v1;
        }
    }
}

// ===== FUSED: gated tri-dilated dwconv + instance norm + ReLU6 + residual + GAP =====
// One block per (n,c) plane. zs = z plane with halo-4 (120x120), ys = dwconv output.
#define ZS_W 120
#define DWN_SMEM ((ZS_W*ZS_W + HW) * 4)   // 57600*... = 107776 bytes

__global__ void __launch_bounds__(256) dwnorm_kernel(const float* __restrict__ w,
                                                     const float* __restrict__ bias,
                                                     const float* __restrict__ gamma,
                                                     const float* __restrict__ beta,
                                                     float* __restrict__ h, int t) {
    extern __shared__ float smf[];
    float* zs = smf;                  // [120][120]
    float* ys = smf + ZS_W*ZS_W;      // [HW]
    __shared__ float red[256];
    __shared__ float redq[256];
    __shared__ float bc[2];           // mean, scale

    int nc = blockIdx.x;
    int n = nc >> 7, c = nc & 127;
    int tid = threadIdx.x;
    const float* zb = g_z + (size_t)nc * HW;

    // load z plane with halo 4 (zero-padded)
    for (int s = tid; s < ZS_W*ZS_W; s += 256) {
        int sy = s / ZS_W, sx = s - sy*ZS_W;
        int gy = sy - 4, gx = sx - 4;
        float v = 0.f;
        if ((unsigned)gy < (unsigned)HH && (unsigned)gx < (unsigned)WW)
            v = zb[gy*WW + gx];
        zs[s] = v;
    }
    float wk[9];
#pragma unroll
    for (int k = 0; k < 9; k++) wk[k] = w[c*9 + k];
    float g0 = g_gates[n*3+0], g1 = g_gates[n*3+1], g2 = g_gates[n*3+2];
    float bi = bias[c];
    __syncthreads();

    // dwconv + local stats
    float lsum = 0.f, lsq = 0.f;
    for (int p = tid; p < HW; p += 256) {
        int py = p / WW, px = p - py*WW;
        const float* zc = zs + (py+4)*ZS_W + (px+4);
        float s1 = 0.f, s2 = 0.f, s4 = 0.f;
#pragma unroll
        for (int ky = 0; ky < 3; ky++)
#pragma unroll
            for (int kx = 0; kx < 3; kx++) {
                float wv = wk[ky*3 + kx];
                int dy = ky - 1, dx = kx - 1;
                s1 += wv * zc[dy*ZS_W + dx];
                s2 += wv * zc[2*dy*ZS_W + 2*dx];
                s4 += wv * zc[4*dy*ZS_W + 4*dx];
            }
        float acc = bi + g0*s1 + g1*s2 + g2*s4;
        ys[p] = acc;
        lsum += acc;
        lsq  += acc * acc;
    }
    red[tid] = lsum;
    redq[tid] = lsq;
    __syncthreads();
    for (int o = 128; o > 0; o >>= 1) {
        if (tid < o) { red[tid] += red[tid + o]; redq[tid] += redq[tid + o]; }
        __syncthreads();
    }
    if (tid == 0) {
        float mean = red[0] * (1.f / (float)HW);
        float var  = redq[0] * (1.f / (float)HW) - mean*mean;
        bc[0] = mean;
        bc[1] = rsqrtf(var + 1e-5f) * gamma[t*CH + c];
    }
    __syncthreads();
    float mean = bc[0], sc = bc[1], bt = beta[t*CH + c];

    // normalize + ReLU6 + residual + GAP
    float4* hp = (float4*)(h + (size_t)nc * HW);
    const float4* yp = (const float4*)ys;
    float gs = 0.f;
    for (int i = tid; i < HW/4; i += 256) {
        float4 y = yp[i];
        float4 hv = hp[i];
        float v;
        v = (y.x - mean)*sc + bt; v = fminf(fmaxf(v, 0.f), 6.f); hv.x += v;
        v = (y.y - mean)*sc + bt; v = fminf(fmaxf(v, 0.f), 6.f); hv.y += v;
        v = (y.z - mean)*sc + bt; v = fminf(fmaxf(v, 0.f), 6.f); hv.z += v;
        v = (y.w - mean)*sc + bt; v = fminf(fmaxf(v, 0.f), 6.f); hv.w += v;
        hp[i] = hv;
        gs += (hv.x + hv.y) + (hv.z + hv.w);
    }
    __syncthreads();   // red reuse
    red[tid] = gs;
    __syncthreads();
    for (int o = 128; o > 0; o >>= 1) {
        if (tid < o) red[tid] += red[tid + o];
        __syncthreads();
    }
    if (tid == 0) g_gap[nc] = red[0] * (1.f / (float)HW);
}

extern "C" void kernel_launch(void* const* d_in, const int* in_sizes, int n_in,
                              void* d_out, int out_size) {
    const float* x     = (const float*)d_in[0];
    const float* dw_w  = (const float*)d_in[1];
    const float* dw_b  = (const float*)d_in[2];
    const float* sym_w = (const float*)d_in[3];
    const float* sym_b = (const float*)d_in[4];
    const float* gW    = (const float*)d_in[5];
    const float* gb    = (const float*)d_in[6];
    const float* gwe   = (const float*)d_in[7];
    const float* gamma = (const float*)d_in[8];
    const float* beta  = (const float*)d_in[9];
    float* h = (float*)d_out;

    cudaFuncSetAttribute(symconv_mma, cudaFuncAttributeMaxDynamicSharedMemorySize, SYM_SMEM);
    cudaFuncSetAttribute(dwnorm_kernel, cudaFuncAttributeMaxDynamicSharedMemorySize, DWN_SMEM);

    copy_gap_kernel<<<NC, 256>>>(x, h);
    wsym_kernel<<<CH*CH/256, 256>>>(sym_w);

    for (int t = 0; t < 4; t++) {
        ent_kernel<<<NB*PP*ECN, 256>>>(h);
        gate_kernel<<<1, 32>>>(gW, gb, gwe);
        symconv_mma<<<dim3(HW/128, NB), 256, SYM_SMEM>>>(h, sym_b);
        dwnorm_kernel<<<NC, 256, DWN_SMEM>>>(dw_w, dw_b, gamma, beta, h, t);
    }
}

// round 12
// speedup vs baseline: 1.9553x; 1.1172x over previous
#include <cuda_runtime.h>
#include <math.h>
#include <stdint.h>

#define NB 8
#define CH 128
#define HH 112
#define WW 112
#define HW (HH*WW)          // 12544
#define NC (NB*CH)          // 1024
#define TOT (NB*CH*HW)      // 12,845,056
#define PP 37               // pooled dim (112/3)
#define NPOOL (PP*PP)       // 1369

// ---- scratch (device globals; no allocation in kernel_launch) ----
__device__ float g_z[TOT];       // sym-conv output
__device__ float g_wsym[CH*CH];  // tf32-rounded symmetric weight
__device__ float g_gap[2][NC];   // parity double-buffered GAP (read t&1, write (t+1)&1)
__device__ float g_ent[2][NB];   // parity double-buffered entropy accumulator

__device__ __forceinline__ uint32_t tf32r(float x) {
    uint32_t u;
    asm("cvt.rna.tf32.f32 %0, %1;" : "=r"(u) : "f"(x));
    return u;
}
__device__ __forceinline__ void mma8(float* c, const uint32_t* a, const uint32_t* b) {
    asm volatile(
        "mma.sync.aligned.m16n8k8.row.col.f32.tf32.tf32.f32 "
        "{%0,%1,%2,%3}, {%4,%5,%6,%7}, {%8,%9}, {%0,%1,%2,%3};"
        : "+f"(c[0]), "+f"(c[1]), "+f"(c[2]), "+f"(c[3])
        : "r"(a[0]), "r"(a[1]), "r"(a[2]), "r"(a[3]), "r"(b[0]), "r"(b[1]));
}

// ========= copy x -> h, fused GAP (slot 0) for iter 0, clears ent slots =========
__global__ void copy_gap_kernel(const float* __restrict__ x, float* __restrict__ h) {
    int nc = blockIdx.x;
    const float4* xp = (const float4*)(x + (size_t)nc * HW);
    float4* hp = (float4*)(h + (size_t)nc * HW);
    float s = 0.f;
    for (int i = threadIdx.x; i < HW/4; i += 256) {
        float4 v = xp[i];
        hp[i] = v;
        s += (v.x + v.y) + (v.z + v.w);
    }
    __shared__ float red[256];
    red[threadIdx.x] = s;
    __syncthreads();
    for (int o = 128; o > 0; o >>= 1) {
        if (threadIdx.x < o) red[threadIdx.x] += red[threadIdx.x + o];
        __syncthreads();
    }
    if (threadIdx.x == 0) {
        g_gap[0][nc] = red[0] * (1.f / (float)HW);
        if (nc < NB) { g_ent[0][nc] = 0.f; g_ent[1][nc] = 0.f; }
    }
}

// ================= symmetrize W (+ tf32 rounding) =================
__global__ void wsym_kernel(const float* __restrict__ W) {
    int i = blockIdx.x * 256 + threadIdx.x;   // 16384
    int d = i >> 7, c = i & 127;
    uint32_t u = tf32r(0.5f * (W[d*CH + c] + W[c*CH + d]));
    g_wsym[i] = __uint_as_float(u);
}

// ================= entropy: block per (n, pooled-row, px-chunk) =================
#define EC 10   // px chunk width
#define ECN 4   // chunks per row (10,10,10,7)
__global__ void __launch_bounds__(256) ent_kernel(const float* __restrict__ h, int par) {
    __shared__ float pooled[CH][EC+1];
    __shared__ float er[8];
    int b = blockIdx.x;
    int s = b & 3;
    int npy = b >> 2;
    int n = npy / PP;
    int py = npy - n * PP;
    int px0 = s * EC;
    int pw = min(EC, PP - px0);
    int tid = threadIdx.x, wid = tid >> 5, lane = tid & 31;
    const float* hn = h + (size_t)n * CH * HW + (3*py) * WW + 3*px0;

    for (int idx = tid; idx < CH * pw; idx += 256) {
        int c = idx / pw, px = idx - c * pw;
        const float* p = hn + (size_t)c * HW + 3*px;
        float v = 0.f;
#pragma unroll
        for (int r = 0; r < 3; r++) v += p[r*WW] + p[r*WW+1] + p[r*WW+2];
        pooled[c][px] = v * (1.f/9.f);
    }
    __syncthreads();

    float esum = 0.f;
    for (int px = wid; px < pw; px += 8) {
        float v[4];
#pragma unroll
        for (int j = 0; j < 4; j++) v[j] = pooled[j*32 + lane][px];
        float m = fmaxf(fmaxf(v[0], v[1]), fmaxf(v[2], v[3]));
#pragma unroll
        for (int o = 16; o > 0; o >>= 1) m = fmaxf(m, __shfl_xor_sync(0xffffffffu, m, o));
        float ss = 0.f;
#pragma unroll
        for (int j = 0; j < 4; j++) ss += expf(v[j] - m);
#pragma unroll
        for (int o = 16; o > 0; o >>= 1) ss += __shfl_xor_sync(0xffffffffu, ss, o);
        float lse = m + logf(ss);
        float e = 0.f;
#pragma unroll
        for (int j = 0; j < 4; j++) {
            float lp = v[j] - lse;
            e -= expf(lp) * lp;
        }
#pragma unroll
        for (int o = 16; o > 0; o >>= 1) e += __shfl_xor_sync(0xffffffffu, e, o);
        if (lane == 0) esum += e;
    }
    if (lane == 0) er[wid] = esum;
    __syncthreads();
    if (tid == 0) {
        float t = 0.f;
#pragma unroll
        for (int i = 0; i < 8; i++) t += er[i];
        atomicAdd(&g_ent[par][n], t);
    }
}

// ============ symmetric 1x1 conv via mma.sync tf32, K-chunked (2 CTAs/SM) ============
#define SST 36                       // 36 == 4 mod 32 -> conflict-free fragment reads
#define SYM_SMEM (2 * 128 * SST * 4) // 36864 bytes

__global__ void __launch_bounds__(256, 2) symconv_mma(const float* __restrict__ h,
                                                      const float* __restrict__ bias) {
    extern __shared__ float sm[];
    float* As = sm;                 // [m][k_chunk]   128 x SST
    float* Bs = sm + 128 * SST;     // [pix][k_chunk] 128 x SST
    int tid = threadIdx.x, lane = tid & 31, wid = tid >> 5;
    int n = blockIdx.y, p0 = blockIdx.x * 128;
    const float* hb = h + (size_t)n * CH * HW + p0;

    int m0 = (wid & 3) * 32;
    int n0 = (wid >> 2) * 64;
    int gr = lane >> 2, tg = lane & 3;

    float acc[2][8][4];
#pragma unroll
    for (int i = 0; i < 2; i++)
#pragma unroll
        for (int j = 0; j < 8; j++)
#pragma unroll
            for (int r = 0; r < 4; r++) acc[i][j][r] = 0.f;

    for (int k0 = 0; k0 < CH; k0 += 32) {
        for (int idx = tid; idx < 4096; idx += 256) {
            int m = idx >> 5, kk = idx & 31;
            As[m*SST + kk] = g_wsym[m*CH + k0 + kk];
        }
        for (int idx = tid; idx < 4096; idx += 256) {
            int pix = idx & 127, kk = idx >> 7;
            Bs[pix*SST + kk] = __uint_as_float(tf32r(hb[(size_t)(k0 + kk) * HW + pix]));
        }
        __syncthreads();

#pragma unroll
        for (int ks = 0; ks < 4; ks++) {
            int kc = ks * 8;
            uint32_t a[2][4], b[8][2];
#pragma unroll
            for (int i = 0; i < 2; i++) {
                const float* ap = &As[(m0 + i*16 + gr)*SST + kc + tg];
                a[i][0] = __float_as_uint(ap[0]);
                a[i][1] = __float_as_uint(ap[8*SST]);
                a[i][2] = __float_as_uint(ap[4]);
                a[i][3] = __float_as_uint(ap[8*SST + 4]);
            }
#pragma unroll
            for (int j = 0; j < 8; j++) {
                const float* bp = &Bs[(n0 + j*8 + gr)*SST + kc + tg];
                b[j][0] = __float_as_uint(bp[0]);
                b[j][1] = __float_as_uint(bp[4]);
            }
#pragma unroll
            for (int i = 0; i < 2; i++)
#pragma unroll
                for (int j = 0; j < 8; j++)
                    mma8(acc[i][j], a[i], b[j]);
        }
        __syncthreads();
    }

    float* zb = g_z + (size_t)n * CH * HW + p0;
#pragma unroll
    for (int i = 0; i < 2; i++) {
        int r0 = m0 + i*16 + gr;
        float bi0 = bias[r0], bi1 = bias[r0 + 8];
#pragma unroll
        for (int j = 0; j < 8; j++) {
            int col = n0 + j*8 + tg*2;
            float2 v0 = make_float2(acc[i][j][0] + bi0, acc[i][j][1] + bi0);
            float2 v1 = make_float2(acc[i][j][2] + bi1, acc[i][j][3] + bi1);
            *(float2*)&zb[(size_t)r0       * HW + col] = v0;
            *(float2*)&zb[(size_t)(r0 + 8) * HW + col] = v1;
        }
    }
}

// ===== FUSED: inline gates + gated tri-dilated dwconv + IS-norm + ReLU6 + residual + GAP =====
// Reads g_gap[t&1], writes g_gap[(t+1)&1]  (no intra-kernel RAW hazard).
#define ZS_W 120
#define DWN_SMEM ((ZS_W*ZS_W + HW) * 4)   // 107776 bytes

__global__ void __launch_bounds__(256) dwnorm_kernel(const float* __restrict__ w,
                                                     const float* __restrict__ bias,
                                                     const float* __restrict__ gamma,
                                                     const float* __restrict__ beta,
                                                     const float* __restrict__ gW,
                                                     const float* __restrict__ gb,
                                                     const float* __restrict__ gwe,
                                                     float* __restrict__ h, int t) {
    extern __shared__ float smf[];
    float* zs = smf;                  // [120][120]
    float* ys = smf + ZS_W*ZS_W;      // [HW]
    __shared__ float red[256];
    __shared__ float redq[256];
    __shared__ float bc[2];           // mean, scale
    __shared__ float bcg[3];          // gates

    int nc = blockIdx.x;
    int n = nc >> 7, c = nc & 127;
    int tid = threadIdx.x, wid = tid >> 5, lane = tid & 31;
    const float* zb = g_z + (size_t)nc * HW;
    int par = t & 1;

    // warp 0: compute this sample's gates from the stable parity slot
    if (wid == 0) {
        const float4 gp = *(const float4*)&g_gap[par][n*CH + lane*4];
        const float* gv = (const float*)&gp;
        float s0 = 0.f, s1 = 0.f, s2 = 0.f;
#pragma unroll
        for (int j = 0; j < 4; j++) {
            int cc = lane*4 + j;
            float val = gv[j];
            s0 += val * gW[cc*3+0];
            s1 += val * gW[cc*3+1];
            s2 += val * gW[cc*3+2];
        }
#pragma unroll
        for (int o = 16; o > 0; o >>= 1) {
            s0 += __shfl_xor_sync(0xffffffffu, s0, o);
            s1 += __shfl_xor_sync(0xffffffffu, s1, o);
            s2 += __shfl_xor_sync(0xffffffffu, s2, o);
        }
        if (lane == 0) {
            float ent = g_ent[par][n] * (1.f / (float)NPOOL);
            float l0 = s0 + gb[0] + ent*gwe[0];
            float l1 = s1 + gb[1] + ent*gwe[1];
            float l2 = s2 + gb[2] + ent*gwe[2];
            float m = fmaxf(l0, fmaxf(l1, l2));
            float e0 = expf(l0-m), e1 = expf(l1-m), e2 = expf(l2-m);
            float inv = 1.f / (e0 + e1 + e2);
            bcg[0] = e0*inv; bcg[1] = e1*inv; bcg[2] = e2*inv;
        }
    }

    // load z plane with halo 4 (zero-padded)
    for (int s = tid; s < ZS_W*ZS_W; s += 256) {
        int sy = s / ZS_W, sx = s - sy*ZS_W;
        int gy = sy - 4, gx = sx - 4;
        float v = 0.f;
        if ((unsigned)gy < (unsigned)HH && (unsigned)gx < (unsigned)WW)
            v = zb[gy*WW + gx];
        zs[s] = v;
    }
    float wk[9];
#pragma unroll
    for (int k = 0; k < 9; k++) wk[k] = w[c*9 + k];
    float bi = bias[c];
    __syncthreads();
    float g0 = bcg[0], g1 = bcg[1], g2 = bcg[2];

    // dwconv + local stats
    float lsum = 0.f, lsq = 0.f;
    for (int p = tid; p < HW; p += 256) {
        int py = p / WW, px = p - py*WW;
        const float* zc = zs + (py+4)*ZS_W + (px+4);
        float s1 = 0.f, s2 = 0.f, s4 = 0.f;
#pragma unroll
        for (int ky = 0; ky < 3; ky++)
#pragma unroll
            for (int kx = 0; kx < 3; kx++) {
                float wv = wk[ky*3 + kx];
                int dy = ky - 1, dx = kx - 1;
                s1 += wv * zc[dy*ZS_W + dx];
                s2 += wv * zc[2*dy*ZS_W + 2*dx];
                s4 += wv * zc[4*dy*ZS_W + 4*dx];
            }
        float acc = bi + g0*s1 + g1*s2 + g2*s4;
        ys[p] = acc;
        lsum += acc;
        lsq  += acc * acc;
    }
    red[tid] = lsum;
    redq[tid] = lsq;
    __syncthreads();
    for (int o = 128; o > 0; o >>= 1) {
        if (tid < o) { red[tid] += red[tid + o]; redq[tid] += redq[tid + o]; }
        __syncthreads();
    }
    if (tid == 0) {
        float mean = red[0] * (1.f / (float)HW);
        float var  = redq[0] * (1.f / (float)HW) - mean*mean;
        bc[0] = mean;
        bc[1] = rsqrtf(var + 1e-5f) * gamma[t*CH + c];
    }
    __syncthreads();
    float mean = bc[0], sc = bc[1], bt = beta[t*CH + c];

    // normalize + ReLU6 + residual + GAP (into the other parity slot)
    float4* hp = (float4*)(h + (size_t)nc * HW);
    const float4* yp = (const float4*)ys;
    float gs = 0.f;
    for (int i = tid; i < HW/4; i += 256) {
        float4 y = yp[i];
        float4 hv = hp[i];
        float v;
        v = (y.x - mean)*sc + bt; v = fminf(fmaxf(v, 0.f), 6.f); hv.x += v;
        v = (y.y - mean)*sc + bt; v = fminf(fmaxf(v, 0.f), 6.f); hv.y += v;
        v = (y.z - mean)*sc + bt; v = fminf(fmaxf(v, 0.f), 6.f); hv.z += v;
        v = (y.w - mean)*sc + bt; v = fminf(fmaxf(v, 0.f), 6.f); hv.w += v;
        hp[i] = hv;
        gs += (hv.x + hv.y) + (hv.z + hv.w);
    }
    __syncthreads();
    red[tid] = gs;
    __syncthreads();
    for (int o = 128; o > 0; o >>= 1) {
        if (tid < o) red[tid] += red[tid + o];
        __syncthreads();
    }
    if (tid == 0) {
        g_gap[par ^ 1][nc] = red[0] * (1.f / (float)HW);
        if (nc < NB) g_ent[par ^ 1][nc] = 0.f;   // re-arm other parity slot
    }
}

extern "C" void kernel_launch(void* const* d_in, const int* in_sizes, int n_in,
                              void* d_out, int out_size) {
    const float* x     = (const float*)d_in[0];
    const float* dw_w  = (const float*)d_in[1];
    const float* dw_b  = (const float*)d_in[2];
    const float* sym_w = (const float*)d_in[3];
    const float* sym_b = (const float*)d_in[4];
    const float* gW    = (const float*)d_in[5];
    const float* gb    = (const float*)d_in[6];
    const float* gwe   = (const float*)d_in[7];
    const float* gamma = (const float*)d_in[8];
    const float* beta  = (const float*)d_in[9];
    float* h = (float*)d_out;

    cudaFuncSetAttribute(symconv_mma, cudaFuncAttributeMaxDynamicSharedMemorySize, SYM_SMEM);
    cudaFuncSetAttribute(dwnorm_kernel, cudaFuncAttributeMaxDynamicSharedMemorySize, DWN_SMEM);

    copy_gap_kernel<<<NC, 256>>>(x, h);
    wsym_kernel<<<CH*CH/256, 256>>>(sym_w);

    for (int t = 0; t < 4; t++) {
        ent_kernel<<<NB*PP*ECN, 256>>>(h, t & 1);
        symconv_mma<<<dim3(HW/128, NB), 256, SYM_SMEM>>>(h, sym_b);
        dwnorm_kernel<<<NC, 256, DWN_SMEM>>>(dw_w, dw_b, gamma, beta, gW, gb, gwe, h, t);
    }
}

// round 14
// speedup vs baseline: 2.2614x; 1.1565x over previous
#include <cuda_runtime.h>
#include <math.h>
#include <stdint.h>

#define NB 8
#define CH 128
#define HH 112
#define WW 112
#define HW (HH*WW)          // 12544
#define NC (NB*CH)          // 1024
#define TOT (NB*CH*HW)      // 12,845,056
#define PP 37               // pooled dim (112/3)
#define NPOOL (PP*PP)       // 1369

// ---- scratch (device globals; no allocation in kernel_launch) ----
__device__ float g_z[TOT];       // sym-conv output
__device__ float g_wsym[CH*CH];  // tf32-rounded symmetric weight
__device__ float g_gap[2][NC];   // parity double-buffered GAP
__device__ float g_ent[2][NB];   // parity double-buffered entropy accumulator

__device__ __forceinline__ uint32_t tf32r(float x) {
    uint32_t u;
    asm("cvt.rna.tf32.f32 %0, %1;" : "=r"(u) : "f"(x));
    return u;
}
__device__ __forceinline__ void mma8(float* c, const uint32_t* a, const uint32_t* b) {
    asm volatile(
        "mma.sync.aligned.m16n8k8.row.col.f32.tf32.tf32.f32 "
        "{%0,%1,%2,%3}, {%4,%5,%6,%7}, {%8,%9}, {%0,%1,%2,%3};"
        : "+f"(c[0]), "+f"(c[1]), "+f"(c[2]), "+f"(c[3])
        : "r"(a[0]), "r"(a[1]), "r"(a[2]), "r"(a[3]), "r"(b[0]), "r"(b[1]));
}

// ========= copy x -> h, fused GAP (slot 0) for iter 0, clears ent slots =========
__global__ void copy_gap_kernel(const float* __restrict__ x, float* __restrict__ h) {
    int nc = blockIdx.x;
    const float4* xp = (const float4*)(x + (size_t)nc * HW);
    float4* hp = (float4*)(h + (size_t)nc * HW);
    float s = 0.f;
    for (int i = threadIdx.x; i < HW/4; i += 256) {
        float4 v = xp[i];
        hp[i] = v;
        s += (v.x + v.y) + (v.z + v.w);
    }
    __shared__ float red[256];
    red[threadIdx.x] = s;
    __syncthreads();
    for (int o = 128; o > 0; o >>= 1) {
        if (threadIdx.x < o) red[threadIdx.x] += red[threadIdx.x + o];
        __syncthreads();
    }
    if (threadIdx.x == 0) {
        g_gap[0][nc] = red[0] * (1.f / (float)HW);
        if (nc < NB) { g_ent[0][nc] = 0.f; g_ent[1][nc] = 0.f; }
    }
}

// ================= symmetrize W (+ tf32 rounding) =================
__global__ void wsym_kernel(const float* __restrict__ W) {
    int i = blockIdx.x * 256 + threadIdx.x;   // 16384
    int d = i >> 7, c = i & 127;
    uint32_t u = tf32r(0.5f * (W[d*CH + c] + W[c*CH + d]));
    g_wsym[i] = __uint_as_float(u);
}

// ================= entropy: block per (n, pooled-row, px-chunk) =================
#define EC 10   // px chunk width
#define ECN 4   // chunks per row
__global__ void __launch_bounds__(256) ent_kernel(const float* __restrict__ h, int par) {
    __shared__ float pooled[CH][EC+1];
    __shared__ float er[8];
    int b = blockIdx.x;
    int s = b & 3;
    int npy = b >> 2;
    int n = npy / PP;
    int py = npy - n * PP;
    int px0 = s * EC;
    int pw = min(EC, PP - px0);
    int tid = threadIdx.x, wid = tid >> 5, lane = tid & 31;
    const float* hn = h + (size_t)n * CH * HW + (3*py) * WW + 3*px0;

    for (int idx = tid; idx < CH * pw; idx += 256) {
        int c = idx / pw, px = idx - c * pw;
        const float* p = hn + (size_t)c * HW + 3*px;
        float v = 0.f;
#pragma unroll
        for (int r = 0; r < 3; r++) v += p[r*WW] + p[r*WW+1] + p[r*WW+2];
        pooled[c][px] = v * (1.f/9.f);
    }
    __syncthreads();

    float esum = 0.f;
    for (int px = wid; px < pw; px += 8) {
        float v[4];
#pragma unroll
        for (int j = 0; j < 4; j++) v[j] = pooled[j*32 + lane][px];
        float m = fmaxf(fmaxf(v[0], v[1]), fmaxf(v[2], v[3]));
#pragma unroll
        for (int o = 16; o > 0; o >>= 1) m = fmaxf(m, __shfl_xor_sync(0xffffffffu, m, o));
        float ss = 0.f;
#pragma unroll
        for (int j = 0; j < 4; j++) ss += expf(v[j] - m);
#pragma unroll
        for (int o = 16; o > 0; o >>= 1) ss += __shfl_xor_sync(0xffffffffu, ss, o);
        float lse = m + logf(ss);
        float e = 0.f;
#pragma unroll
        for (int j = 0; j < 4; j++) {
            float lp = v[j] - lse;
            e -= expf(lp) * lp;
        }
#pragma unroll
        for (int o = 16; o > 0; o >>= 1) e += __shfl_xor_sync(0xffffffffu, e, o);
        if (lane == 0) esum += e;
    }
    if (lane == 0) er[wid] = esum;
    __syncthreads();
    if (tid == 0) {
        float t = 0.f;
#pragma unroll
        for (int i = 0; i < 8; i++) t += er[i];
        atomicAdd(&g_ent[par][n], t);
    }
}

// ======= symmetric 1x1 conv: mma.sync tf32, cp.async double-buffered K-chunks =======
// A chunk: [m][kk] stride 36 (read banks (4gr+tg)%32 distinct).
// B chunk: [kk][pix] stride 136 (read banks (8tg+gr)%32 distinct; fill is contiguous copy).
#define A_ST 36
#define B_ST 136
#define A_CHUNK (128 * A_ST)        // floats: 4608
#define B_CHUNK (32 * B_ST)         // floats: 4352
#define SYM_SMEM ((2*A_CHUNK + 2*B_CHUNK) * 4)   // 71680 bytes

__global__ void __launch_bounds__(256, 2) symconv_mma(const float* __restrict__ h,
                                                      const float* __restrict__ bias) {
    extern __shared__ float sm[];
    int tid = threadIdx.x, lane = tid & 31, wid = tid >> 5;
    int n = blockIdx.y, p0 = blockIdx.x * 128;
    const float* hb = h + (size_t)n * CH * HW + p0;

    uint32_t sbase = (uint32_t)__cvta_generic_to_shared(sm);
    uint32_t smA[2] = { sbase, sbase + A_CHUNK*4 };
    uint32_t smB[2] = { sbase + 2*A_CHUNK*4, sbase + 2*A_CHUNK*4 + B_CHUNK*4 };
    float* fA[2] = { sm, sm + A_CHUNK };
    float* fB[2] = { sm + 2*A_CHUNK, sm + 2*A_CHUNK + B_CHUNK };

#define ISSUE(K0, BUF) do {                                                         \
        uint32_t adst = smA[BUF], bdst = smB[BUF];                                  \
        _Pragma("unroll")                                                           \
        for (int r = 0; r < 4; r++) {                                               \
            int i = tid + 256*r;                                                    \
            int m = i >> 3, kkg = (i & 7) << 2;                                     \
            asm volatile("cp.async.ca.shared.global [%0], [%1], 16;"                \
                :: "r"(adst + (uint32_t)(m*A_ST + kkg)*4u),                         \
                   "l"(&g_wsym[m*CH + (K0) + kkg]) : "memory");                     \
            int kk = i >> 5, pg = (i & 31) << 2;                                    \
            asm volatile("cp.async.ca.shared.global [%0], [%1], 16;"                \
                :: "r"(bdst + (uint32_t)(kk*B_ST + pg)*4u),                         \
                   "l"(hb + (size_t)((K0) + kk)*HW + pg) : "memory");               \
        }                                                                           \
        asm volatile("cp.async.commit_group;" ::: "memory");                        \
    } while (0)

    int m0 = (wid & 3) * 32;
    int n0 = (wid >> 2) * 64;
    int gr = lane >> 2, tg = lane & 3;

    float acc[2][8][4];
#pragma unroll
    for (int i = 0; i < 2; i++)
#pragma unroll
        for (int j = 0; j < 8; j++)
#pragma unroll
            for (int r = 0; r < 4; r++) acc[i][j][r] = 0.f;

#define MMACHUNK(BUF) do {                                                          \
        const float* As = fA[BUF];                                                  \
        const float* Bs = fB[BUF];                                                  \
        _Pragma("unroll")                                                           \
        for (int ks = 0; ks < 4; ks++) {                                            \
            int kc = ks * 8;                                                        \
            uint32_t a[2][4], b[8][2];                                              \
            _Pragma("unroll")                                                       \
            for (int i = 0; i < 2; i++) {                                           \
                const float* ap = &As[(m0 + i*16 + gr)*A_ST + kc + tg];             \
                a[i][0] = __float_as_uint(ap[0]);                                   \
                a[i][1] = __float_as_uint(ap[8*A_ST]);                              \
                a[i][2] = __float_as_uint(ap[4]);                                   \
                a[i][3] = __float_as_uint(ap[8*A_ST + 4]);                          \
            }                                                                       \
            _Pragma("unroll")                                                       \
            for (int j = 0; j < 8; j++) {                                           \
                const float* bp = &Bs[(kc + tg)*B_ST + n0 + j*8 + gr];              \
                b[j][0] = tf32r(bp[0]);                                             \
                b[j][1] = tf32r(bp[4*B_ST]);                                        \
            }                                                                       \
            _Pragma("unroll")                                                       \
            for (int i = 0; i < 2; i++)                                             \
                _Pragma("unroll")                                                   \
                for (int j = 0; j < 8; j++)                                         \
                    mma8(acc[i][j], a[i], b[j]);                                    \
        }                                                                           \
    } while (0)

    ISSUE(0, 0);
    ISSUE(32, 1);
    asm volatile("cp.async.wait_group 1;" ::: "memory");
    __syncthreads();
    MMACHUNK(0);
    __syncthreads();
    ISSUE(64, 0);
    asm volatile("cp.async.wait_group 1;" ::: "memory");
    __syncthreads();
    MMACHUNK(1);
    __syncthreads();
    ISSUE(96, 1);
    asm volatile("cp.async.wait_group 1;" ::: "memory");
    __syncthreads();
    MMACHUNK(0);
    __syncthreads();
    asm volatile("cp.async.wait_group 0;" ::: "memory");
    __syncthreads();
    MMACHUNK(1);

    float* zb = g_z + (size_t)n * CH * HW + p0;
#pragma unroll
    for (int i = 0; i < 2; i++) {
        int r0 = m0 + i*16 + gr;
        float bi0 = bias[r0], bi1 = bias[r0 + 8];
#pragma unroll
        for (int j = 0; j < 8; j++) {
            int col = n0 + j*8 + tg*2;
            float2 v0 = make_float2(acc[i][j][0] + bi0, acc[i][j][1] + bi0);
            float2 v1 = make_float2(acc[i][j][2] + bi1, acc[i][j][3] + bi1);
            *(float2*)&zb[(size_t)r0       * HW + col] = v0;
            *(float2*)&zb[(size_t)(r0 + 8) * HW + col] = v1;
        }
    }
#undef ISSUE
#undef MMACHUNK
}

// ===== FUSED: inline gates + gated tri-dilated dwconv + IS-norm + ReLU6 + residual + GAP =====
#define ZS_W 120
#define DWN_SMEM ((ZS_W*ZS_W + HW) * 4)   // 107776 bytes

__global__ void __launch_bounds__(256) dwnorm_kernel(const float* __restrict__ w,
                                                     const float* __restrict__ bias,
                                                     const float* __restrict__ gamma,
                                                     const float* __restrict__ beta,
                                                     const float* __restrict__ gW,
                                                     const float* __restrict__ gb,
                                                     const float* __restrict__ gwe,
                                                     float* __restrict__ h, int t) {
    extern __shared__ float smf[];
    float* zs = smf;                  // [120][120]
    float* ys = smf + ZS_W*ZS_W;      // [HW]
    __shared__ float red[256];
    __shared__ float redq[256];
    __shared__ float bc[2];           // mean, scale
    __shared__ float bcg[3];          // gates

    int nc = blockIdx.x;
    int n = nc >> 7, c = nc & 127;
    int tid = threadIdx.x, wid = tid >> 5, lane = tid & 31;
    const float* zb = g_z + (size_t)nc * HW;
    int par = t & 1;

    if (wid == 0) {
        const float4 gp = *(const float4*)&g_gap[par][n*CH + lane*4];
        const float* gv = (const float*)&gp;
        float s0 = 0.f, s1 = 0.f, s2 = 0.f;
#pragma unroll
        for (int j = 0; j < 4; j++) {
            int cc = lane*4 + j;
            float val = gv[j];
            s0 += val * gW[cc*3+0];
            s1 += val * gW[cc*3+1];
            s2 += val * gW[cc*3+2];
        }
#pragma unroll
        for (int o = 16; o > 0; o >>= 1) {
            s0 += __shfl_xor_sync(0xffffffffu, s0, o);
            s1 += __shfl_xor_sync(0xffffffffu, s1, o);
            s2 += __shfl_xor_sync(0xffffffffu, s2, o);
        }
        if (lane == 0) {
            float ent = g_ent[par][n] * (1.f / (float)NPOOL);
            float l0 = s0 + gb[0] + ent*gwe[0];
            float l1 = s1 + gb[1] + ent*gwe[1];
            float l2 = s2 + gb[2] + ent*gwe[2];
            float m = fmaxf(l0, fmaxf(l1, l2));
            float e0 = expf(l0-m), e1 = expf(l1-m), e2 = expf(l2-m);
            float inv = 1.f / (e0 + e1 + e2);
            bcg[0] = e0*inv; bcg[1] = e1*inv; bcg[2] = e2*inv;
        }
    }

    for (int s = tid; s < ZS_W*ZS_W; s += 256) {
        int sy = s / ZS_W, sx = s - sy*ZS_W;
        int gy = sy - 4, gx = sx - 4;
        float v = 0.f;
        if ((unsigned)gy < (unsigned)HH && (unsigned)gx < (unsigned)WW)
            v = zb[gy*WW + gx];
        zs[s] = v;
    }
    float wk[9];
#pragma unroll
    for (int k = 0; k < 9; k++) wk[k] = w[c*9 + k];
    float bi = bias[c];
    __syncthreads();
    float g0 = bcg[0], g1 = bcg[1], g2 = bcg[2];

    float lsum = 0.f, lsq = 0.f;
    for (int p = tid; p < HW; p += 256) {
        int py = p / WW, px = p - py*WW;
        const float* zc = zs + (py+4)*ZS_W + (px+4);
        float s1 = 0.f, s2 = 0.f, s4 = 0.f;
#pragma unroll
        for (int ky = 0; ky < 3; ky++)
#pragma unroll
            for (int kx = 0; kx < 3; kx++) {
                float wv = wk[ky*3 + kx];
                int dy = ky - 1, dx = kx - 1;
                s1 += wv * zc[dy*ZS_W + dx];
                s2 += wv * zc[2*dy*ZS_W + 2*dx];
                s4 += wv * zc[4*dy*ZS_W + 4*dx];
            }
        float acc = bi + g0*s1 + g1*s2 + g2*s4;
        ys[p] = acc;
        lsum += acc;
        lsq  += acc * acc;
    }
    red[tid] = lsum;
    redq[tid] = lsq;
    __syncthreads();
    for (int o = 128; o > 0; o >>= 1) {
        if (tid < o) { red[tid] += red[tid + o]; redq[tid] += redq[tid + o]; }
        __syncthreads();
    }
    if (tid == 0) {
        float mean = red[0] * (1.f / (float)HW);
        float var  = redq[0] * (1.f / (float)HW) - mean*mean;
        bc[0] = mean;
        bc[1] = rsqrtf(var + 1e-5f) * gamma[t*CH + c];
    }
    __syncthreads();
    float mean = bc[0], sc = bc[1], bt = beta[t*CH + c];

    float4* hp = (float4*)(h + (size_t)nc * HW);
    const float4* yp = (const float4*)ys;
    float gs = 0.f;
    for (int i = tid; i < HW/4; i += 256) {
        float4 y = yp[i];
        float4 hv = hp[i];
        float v;
        v = (y.x - mean)*sc + bt; v = fminf(fmaxf(v, 0.f), 6.f); hv.x += v;
        v = (y.y - mean)*sc + bt; v = fminf(fmaxf(v, 0.f), 6.f); hv.y += v;
        v = (y.z - mean)*sc + bt; v = fminf(fmaxf(v, 0.f), 6.f); hv.z += v;
        v = (y.w - mean)*sc + bt; v = fminf(fmaxf(v, 0.f), 6.f); hv.w += v;
        hp[i] = hv;
        gs += (hv.x + hv.y) + (hv.z + hv.w);
    }
    __syncthreads();
    red[tid] = gs;
    __syncthreads();
    for (int o = 128; o > 0; o >>= 1) {
        if (tid < o) red[tid] += red[tid + o];
        __syncthreads();
    }
    if (tid == 0) {
        g_gap[par ^ 1][nc] = red[0] * (1.f / (float)HW);
        if (nc < NB) g_ent[par ^ 1][nc] = 0.f;
    }
}

extern "C" void kernel_launch(void* const* d_in, const int* in_sizes, int n_in,
                              void* d_out, int out_size) {
    const float* x     = (const float*)d_in[0];
    const float* dw_w  = (const float*)d_in[1];
    const float* dw_b  = (const float*)d_in[2];
    const float* sym_w = (const float*)d_in[3];
    const float* sym_b = (const float*)d_in[4];
    const float* gW    = (const float*)d_in[5];
    const float* gb    = (const float*)d_in[6];
    const float* gwe   = (const float*)d_in[7];
    const float* gamma = (const float*)d_in[8];
    const float* beta  = (const float*)d_in[9];
    float* h = (float*)d_out;

    cudaFuncSetAttribute(symconv_mma, cudaFuncAttributeMaxDynamicSharedMemorySize, SYM_SMEM);
    cudaFuncSetAttribute(dwnorm_kernel, cudaFuncAttributeMaxDynamicSharedMemorySize, DWN_SMEM);

    copy_gap_kernel<<<NC, 256>>>(x, h);
    wsym_kernel<<<CH*CH/256, 256>>>(sym_w);

    for (int t = 0; t < 4; t++) {
        ent_kernel<<<NB*PP*ECN, 256>>>(h, t & 1);
        symconv_mma<<<dim3(HW/128, NB), 256, SYM_SMEM>>>(h, sym_b);
        dwnorm_kernel<<<NC, 256, DWN_SMEM>>>(dw_w, dw_b, gamma, beta, gW, gb, gwe, h, t);
    }
}

// round 15
// speedup vs baseline: 3.0116x; 1.3317x over previous
#include <cuda_runtime.h>
#include <math.h>
#include <stdint.h>

#define NB 8
#define CH 128
#define HH 112
#define WW 112
#define HW (HH*WW)          // 12544
#define NC (NB*CH)          // 1024
#define TOT (NB*CH*HW)      // 12,845,056
#define PP 37               // pooled dim (112/3)
#define NPOOL (PP*PP)       // 1369

// ---- scratch (device globals; no allocation in kernel_launch) ----
__device__ float g_z[TOT];       // sym-conv output
__device__ float g_wsym[CH*CH];  // tf32-rounded symmetric weight
__device__ float g_gap[2][NC];   // parity double-buffered GAP
__device__ float g_ent[2][NB];   // parity double-buffered entropy accumulator

__device__ __forceinline__ uint32_t tf32r(float x) {
    uint32_t u;
    asm("cvt.rna.tf32.f32 %0, %1;" : "=r"(u) : "f"(x));
    return u;
}
__device__ __forceinline__ void mma8(float* c, const uint32_t* a, const uint32_t* b) {
    asm volatile(
        "mma.sync.aligned.m16n8k8.row.col.f32.tf32.tf32.f32 "
        "{%0,%1,%2,%3}, {%4,%5,%6,%7}, {%8,%9}, {%0,%1,%2,%3};"
        : "+f"(c[0]), "+f"(c[1]), "+f"(c[2]), "+f"(c[3])
        : "r"(a[0]), "r"(a[1]), "r"(a[2]), "r"(a[3]), "r"(b[0]), "r"(b[1]));
}

// ========= copy x -> h, fused GAP (slot 0) for iter 0, clears ent slots =========
__global__ void copy_gap_kernel(const float* __restrict__ x, float* __restrict__ h) {
    int nc = blockIdx.x;
    const float4* xp = (const float4*)(x + (size_t)nc * HW);
    float4* hp = (float4*)(h + (size_t)nc * HW);
    float s = 0.f;
    for (int i = threadIdx.x; i < HW/4; i += 256) {
        float4 v = xp[i];
        hp[i] = v;
        s += (v.x + v.y) + (v.z + v.w);
    }
    __shared__ float red[256];
    red[threadIdx.x] = s;
    __syncthreads();
    for (int o = 128; o > 0; o >>= 1) {
        if (threadIdx.x < o) red[threadIdx.x] += red[threadIdx.x + o];
        __syncthreads();
    }
    if (threadIdx.x == 0) {
        g_gap[0][nc] = red[0] * (1.f / (float)HW);
        if (nc < NB) { g_ent[0][nc] = 0.f; g_ent[1][nc] = 0.f; }
    }
}

// ================= symmetrize W (+ tf32 rounding) =================
__global__ void wsym_kernel(const float* __restrict__ W) {
    int i = blockIdx.x * 256 + threadIdx.x;   // 16384
    int d = i >> 7, c = i & 127;
    uint32_t u = tf32r(0.5f * (W[d*CH + c] + W[c*CH + d]));
    g_wsym[i] = __uint_as_float(u);
}

// ================= entropy: block per (n, pooled-row, px-chunk) =================
#define EC 10   // px chunk width
#define ECN 4   // chunks per row
__global__ void __launch_bounds__(256) ent_kernel(const float* __restrict__ h, int par) {
    __shared__ float pooled[CH][EC+1];
    __shared__ float er[8];
    int b = blockIdx.x;
    int s = b & 3;
    int npy = b >> 2;
    int n = npy / PP;
    int py = npy - n * PP;
    int px0 = s * EC;
    int pw = min(EC, PP - px0);
    int tid = threadIdx.x, wid = tid >> 5, lane = tid & 31;
    const float* hn = h + (size_t)n * CH * HW + (3*py) * WW + 3*px0;

    for (int idx = tid; idx < CH * pw; idx += 256) {
        int c = idx / pw, px = idx - c * pw;
        const float* p = hn + (size_t)c * HW + 3*px;
        float v = 0.f;
#pragma unroll
        for (int r = 0; r < 3; r++) v += p[r*WW] + p[r*WW+1] + p[r*WW+2];
        pooled[c][px] = v * (1.f/9.f);
    }
    __syncthreads();

    float esum = 0.f;
    for (int px = wid; px < pw; px += 8) {
        float v[4];
#pragma unroll
        for (int j = 0; j < 4; j++) v[j] = pooled[j*32 + lane][px];
        float m = fmaxf(fmaxf(v[0], v[1]), fmaxf(v[2], v[3]));
#pragma unroll
        for (int o = 16; o > 0; o >>= 1) m = fmaxf(m, __shfl_xor_sync(0xffffffffu, m, o));
        float ss = 0.f;
#pragma unroll
        for (int j = 0; j < 4; j++) ss += expf(v[j] - m);
#pragma unroll
        for (int o = 16; o > 0; o >>= 1) ss += __shfl_xor_sync(0xffffffffu, ss, o);
        float lse = m + logf(ss);
        float e = 0.f;
#pragma unroll
        for (int j = 0; j < 4; j++) {
            float lp = v[j] - lse;
            e -= expf(lp) * lp;
        }
#pragma unroll
        for (int o = 16; o > 0; o >>= 1) e += __shfl_xor_sync(0xffffffffu, e, o);
        if (lane == 0) esum += e;
    }
    if (lane == 0) er[wid] = esum;
    __syncthreads();
    if (tid == 0) {
        float t = 0.f;
#pragma unroll
        for (int i = 0; i < 8; i++) t += er[i];
        atomicAdd(&g_ent[par][n], t);
    }
}

// ======= symmetric 1x1 conv: mma.sync tf32, cp.async double-buffered K-chunks =======
#define A_ST 36
#define B_ST 136
#define A_CHUNK (128 * A_ST)
#define B_CHUNK (32 * B_ST)
#define SYM_SMEM ((2*A_CHUNK + 2*B_CHUNK) * 4)   // 71680 bytes

__global__ void __launch_bounds__(256, 2) symconv_mma(const float* __restrict__ h,
                                                      const float* __restrict__ bias) {
    extern __shared__ float sm[];
    int tid = threadIdx.x, lane = tid & 31, wid = tid >> 5;
    int n = blockIdx.y, p0 = blockIdx.x * 128;
    const float* hb = h + (size_t)n * CH * HW + p0;

    uint32_t sbase = (uint32_t)__cvta_generic_to_shared(sm);
    uint32_t smA[2] = { sbase, sbase + A_CHUNK*4 };
    uint32_t smB[2] = { sbase + 2*A_CHUNK*4, sbase + 2*A_CHUNK*4 + B_CHUNK*4 };
    float* fA[2] = { sm, sm + A_CHUNK };
    float* fB[2] = { sm + 2*A_CHUNK, sm + 2*A_CHUNK + B_CHUNK };

#define ISSUE(K0, BUF) do {                                                         \
        uint32_t adst = smA[BUF], bdst = smB[BUF];                                  \
        _Pragma("unroll")                                                           \
        for (int r = 0; r < 4; r++) {                                               \
            int i = tid + 256*r;                                                    \
            int m = i >> 3, kkg = (i & 7) << 2;                                     \
            asm volatile("cp.async.ca.shared.global [%0], [%1], 16;"                \
                :: "r"(adst + (uint32_t)(m*A_ST + kkg)*4u),                         \
                   "l"(&g_wsym[m*CH + (K0) + kkg]) : "memory");                     \
            int kk = i >> 5, pg = (i & 31) << 2;                                    \
            asm volatile("cp.async.ca.shared.global [%0], [%1], 16;"                \
                :: "r"(bdst + (uint32_t)(kk*B_ST + pg)*4u),                         \
                   "l"(hb + (size_t)((K0) + kk)*HW + pg) : "memory");               \
        }                                                                           \
        asm volatile("cp.async.commit_group;" ::: "memory");                        \
    } while (0)

    int m0 = (wid & 3) * 32;
    int n0 = (wid >> 2) * 64;
    int gr = lane >> 2, tg = lane & 3;

    float acc[2][8][4];
#pragma unroll
    for (int i = 0; i < 2; i++)
#pragma unroll
        for (int j = 0; j < 8; j++)
#pragma unroll
            for (int r = 0; r < 4; r++) acc[i][j][r] = 0.f;

#define MMACHUNK(BUF) do {                                                          \
        const float* As = fA[BUF];                                                  \
        const float* Bs = fB[BUF];                                                  \
        _Pragma("unroll")                                                           \
        for (int ks = 0; ks < 4; ks++) {                                            \
            int kc = ks * 8;                                                        \
            uint32_t a[2][4], b[8][2];                                              \
            _Pragma("unroll")                                                       \
            for (int i = 0; i < 2; i++) {                                           \
                const float* ap = &As[(m0 + i*16 + gr)*A_ST + kc + tg];             \
                a[i][0] = __float_as_uint(ap[0]);                                   \
                a[i][1] = __float_as_uint(ap[8*A_ST]);                              \
                a[i][2] = __float_as_uint(ap[4]);                                   \
                a[i][3] = __float_as_uint(ap[8*A_ST + 4]);                          \
            }                                                                       \
            _Pragma("unroll")                                                       \
            for (int j = 0; j < 8; j++) {                                           \
                const float* bp = &Bs[(kc + tg)*B_ST + n0 + j*8 + gr];              \
                b[j][0] = tf32r(bp[0]);                                             \
                b[j][1] = tf32r(bp[4*B_ST]);                                        \
            }                                                                       \
            _Pragma("unroll")                                                       \
            for (int i = 0; i < 2; i++)                                             \
                _Pragma("unroll")                                                   \
                for (int j = 0; j < 8; j++)                                         \
                    mma8(acc[i][j], a[i], b[j]);                                    \
        }                                                                           \
    } while (0)

    ISSUE(0, 0);
    ISSUE(32, 1);
    asm volatile("cp.async.wait_group 1;" ::: "memory");
    __syncthreads();
    MMACHUNK(0);
    __syncthreads();
    ISSUE(64, 0);
    asm volatile("cp.async.wait_group 1;" ::: "memory");
    __syncthreads();
    MMACHUNK(1);
    __syncthreads();
    ISSUE(96, 1);
    asm volatile("cp.async.wait_group 1;" ::: "memory");
    __syncthreads();
    MMACHUNK(0);
    __syncthreads();
    asm volatile("cp.async.wait_group 0;" ::: "memory");
    __syncthreads();
    MMACHUNK(1);

    float* zb = g_z + (size_t)n * CH * HW + p0;
#pragma unroll
    for (int i = 0; i < 2; i++) {
        int r0 = m0 + i*16 + gr;
        float bi0 = bias[r0], bi1 = bias[r0 + 8];
#pragma unroll
        for (int j = 0; j < 8; j++) {
            int col = n0 + j*8 + tg*2;
            float2 v0 = make_float2(acc[i][j][0] + bi0, acc[i][j][1] + bi0);
            float2 v1 = make_float2(acc[i][j][2] + bi1, acc[i][j][3] + bi1);
            *(float2*)&zb[(size_t)r0       * HW + col] = v0;
            *(float2*)&zb[(size_t)(r0 + 8) * HW + col] = v1;
        }
    }
#undef ISSUE
#undef MMACHUNK
}

// ===== FUSED: inline gates + gated tri-dilated dwconv + IS-norm + ReLU6 + residual + GAP =====
// 512 threads; y kept in registers (25/thread); smem = z halo plane only.
#define ZS_W 120
#define DWT 512
#define PPT 25                             // ceil(HW/DWT)
#define DWN_SMEM (ZS_W*ZS_W * 4)           // 57600 bytes

__global__ void __launch_bounds__(DWT, 2) dwnorm_kernel(const float* __restrict__ w,
                                                        const float* __restrict__ bias,
                                                        const float* __restrict__ gamma,
                                                        const float* __restrict__ beta,
                                                        const float* __restrict__ gW,
                                                        const float* __restrict__ gb,
                                                        const float* __restrict__ gwe,
                                                        float* __restrict__ h, int t) {
    extern __shared__ float smf[];
    float* zs = smf;                  // [120][120]
    __shared__ float red[DWT];
    __shared__ float redq[DWT];
    __shared__ float bc[2];           // mean, scale
    __shared__ float bcg[3];          // gates

    int nc = blockIdx.x;
    int n = nc >> 7, c = nc & 127;
    int tid = threadIdx.x, wid = tid >> 5, lane = tid & 31;
    const float* zb = g_z + (size_t)nc * HW;
    int par = t & 1;

    // warp 0: gates for this sample (reads stable parity slots)
    if (wid == 0) {
        const float4 gp = *(const float4*)&g_gap[par][n*CH + lane*4];
        const float* gv = (const float*)&gp;
        float s0 = 0.f, s1 = 0.f, s2 = 0.f;
#pragma unroll
        for (int j = 0; j < 4; j++) {
            int cc = lane*4 + j;
            float val = gv[j];
            s0 += val * gW[cc*3+0];
            s1 += val * gW[cc*3+1];
            s2 += val * gW[cc*3+2];
        }
#pragma unroll
        for (int o = 16; o > 0; o >>= 1) {
            s0 += __shfl_xor_sync(0xffffffffu, s0, o);
            s1 += __shfl_xor_sync(0xffffffffu, s1, o);
            s2 += __shfl_xor_sync(0xffffffffu, s2, o);
        }
        if (lane == 0) {
            float ent = g_ent[par][n] * (1.f / (float)NPOOL);
            float l0 = s0 + gb[0] + ent*gwe[0];
            float l1 = s1 + gb[1] + ent*gwe[1];
            float l2 = s2 + gb[2] + ent*gwe[2];
            float m = fmaxf(l0, fmaxf(l1, l2));
            float e0 = expf(l0-m), e1 = expf(l1-m), e2 = expf(l2-m);
            float inv = 1.f / (e0 + e1 + e2);
            bcg[0] = e0*inv; bcg[1] = e1*inv; bcg[2] = e2*inv;
        }
    }

    // load z plane with halo 4 (zero-padded)
    for (int s = tid; s < ZS_W*ZS_W; s += DWT) {
        int sy = s / ZS_W, sx = s - sy*ZS_W;
        int gy = sy - 4, gx = sx - 4;
        float v = 0.f;
        if ((unsigned)gy < (unsigned)HH && (unsigned)gx < (unsigned)WW)
            v = zb[gy*WW + gx];
        zs[s] = v;
    }
    float wk[9];
#pragma unroll
    for (int k = 0; k < 9; k++) wk[k] = w[c*9 + k];
    float bi = bias[c];
    __syncthreads();
    float g0 = bcg[0], g1 = bcg[1], g2 = bcg[2];

    // dwconv into registers + local stats
    float yreg[PPT];
    float lsum = 0.f, lsq = 0.f;
#pragma unroll
    for (int r = 0; r < PPT; r++) {
        int p = tid + DWT * r;
        if (p < HW) {
            int py = p / WW, px = p - py*WW;
            const float* zc = zs + (py+4)*ZS_W + (px+4);
            float s1 = 0.f, s2 = 0.f, s4 = 0.f;
#pragma unroll
            for (int ky = 0; ky < 3; ky++)
#pragma unroll
                for (int kx = 0; kx < 3; kx++) {
                    float wv = wk[ky*3 + kx];
                    int dy = ky - 1, dx = kx - 1;
                    s1 += wv * zc[dy*ZS_W + dx];
                    s2 += wv * zc[2*dy*ZS_W + 2*dx];
                    s4 += wv * zc[4*dy*ZS_W + 4*dx];
                }
            float acc = bi + g0*s1 + g1*s2 + g2*s4;
            yreg[r] = acc;
            lsum += acc;
            lsq  += acc * acc;
        }
    }
    red[tid] = lsum;
    redq[tid] = lsq;
    __syncthreads();
    for (int o = DWT/2; o > 0; o >>= 1) {
        if (tid < o) { red[tid] += red[tid + o]; redq[tid] += redq[tid + o]; }
        __syncthreads();
    }
    if (tid == 0) {
        float mean = red[0] * (1.f / (float)HW);
        float var  = redq[0] * (1.f / (float)HW) - mean*mean;
        bc[0] = mean;
        bc[1] = rsqrtf(var + 1e-5f) * gamma[t*CH + c];
    }
    __syncthreads();
    float mean = bc[0], sc = bc[1], bt = beta[t*CH + c];

    // normalize + ReLU6 + residual + GAP (coalesced scalar access)
    float* hp = h + (size_t)nc * HW;
    float gs = 0.f;
#pragma unroll
    for (int r = 0; r < PPT; r++) {
        int p = tid + DWT * r;
        if (p < HW) {
            float v = (yreg[r] - mean)*sc + bt;
            v = fminf(fmaxf(v, 0.f), 6.f);
            float hv = hp[p] + v;
            hp[p] = hv;
            gs += hv;
        }
    }
    __syncthreads();
    red[tid] = gs;
    __syncthreads();
    for (int o = DWT/2; o > 0; o >>= 1) {
        if (tid < o) red[tid] += red[tid + o];
        __syncthreads();
    }
    if (tid == 0) {
        g_gap[par ^ 1][nc] = red[0] * (1.f / (float)HW);
        if (nc < NB) g_ent[par ^ 1][nc] = 0.f;
    }
}

extern "C" void kernel_launch(void* const* d_in, const int* in_sizes, int n_in,
                              void* d_out, int out_size) {
    const float* x     = (const float*)d_in[0];
    const float* dw_w  = (const float*)d_in[1];
    const float* dw_b  = (const float*)d_in[2];
    const float* sym_w = (const float*)d_in[3];
    const float* sym_b = (const float*)d_in[4];
    const float* gW    = (const float*)d_in[5];
    const float* gb    = (const float*)d_in[6];
    const float* gwe   = (const float*)d_in[7];
    const float* gamma = (const float*)d_in[8];
    const float* beta  = (const float*)d_in[9];
    float* h = (float*)d_out;

    cudaFuncSetAttribute(symconv_mma, cudaFuncAttributeMaxDynamicSharedMemorySize, SYM_SMEM);
    cudaFuncSetAttribute(dwnorm_kernel, cudaFuncAttributeMaxDynamicSharedMemorySize, DWN_SMEM);

    copy_gap_kernel<<<NC, 256>>>(x, h);
    wsym_kernel<<<CH*CH/256, 256>>>(sym_w);

    for (int t = 0; t < 4; t++) {
        ent_kernel<<<NB*PP*ECN, 256>>>(h, t & 1);
        symconv_mma<<<dim3(HW/128, NB), 256, SYM_SMEM>>>(h, sym_b);
        dwnorm_kernel<<<NC, DWT, DWN_SMEM>>>(dw_w, dw_b, gamma, beta, gW, gb, gwe, h, t);
    }
}